// round 1
// baseline (speedup 1.0000x reference)
#include <cuda_runtime.h>
#include <math.h>

#define BB   2
#define LL   2048
#define DM   1024
#define DI   2048
#define DS   16
#define DTR  64
#define MROWS (BB*LL)          /* 4096 */
#define XPC  (DTR + 2*DS)      /* 96   */

// ---------------- scratch (device globals; no allocation allowed) -----------
__device__ float g_xz   [(size_t)MROWS * 2 * DI];   // 4096 x 4096  (xb | z)
__device__ float g_u    [(size_t)MROWS * DI];       // conv+silu output
__device__ float g_xdbl [(size_t)MROWS * XPC];      // dt_low | B | C
__device__ float g_delta[(size_t)MROWS * DI];       // softplus(dt)
__device__ float g_yg   [(size_t)MROWS * DI];       // gated scan output

// ---------------- generic fp32 NT GEMM: C[M,N] = A[M,K] * B[N,K]^T ----------
// 128x128 block tile, BK=8, 256 threads, 8x8 per-thread microtile.
// ep==1: C = softplus(acc + bias[col])
__global__ __launch_bounds__(256, 2)
void gemm_nt_128(const float* __restrict__ A, int lda,
                 const float* __restrict__ Bw, int ldb,
                 float* __restrict__ C, int ldc,
                 int M, int N, int K,
                 const float* __restrict__ bias, int ep)
{
    __shared__ float As[8][128];
    __shared__ float Bs[8][128];

    const int tid  = threadIdx.x;
    const int brow = blockIdx.y * 128;
    const int bcol = blockIdx.x * 128;
    const int ty   = tid >> 4;        // 0..15
    const int tx   = tid & 15;        // 0..15
    const int lr   = tid >> 1;        // 0..127 loader row
    const int lc   = (tid & 1) << 2;  // 0 or 4 loader col

    float acc[8][8];
#pragma unroll
    for (int i = 0; i < 8; i++)
#pragma unroll
        for (int j = 0; j < 8; j++) acc[i][j] = 0.f;

    const int  arow = brow + lr;
    const int  brw  = bcol + lr;
    const bool aval = (arow < M);
    const bool bval = (brw  < N);
    const float* Aptr = A  + (size_t)arow * lda + lc;
    const float* Bptr = Bw + (size_t)brw  * ldb + lc;

    for (int kt = 0; kt < K; kt += 8) {
        float4 av = aval ? *(const float4*)(Aptr + kt) : make_float4(0.f,0.f,0.f,0.f);
        float4 bv = bval ? *(const float4*)(Bptr + kt) : make_float4(0.f,0.f,0.f,0.f);
        As[lc+0][lr] = av.x; As[lc+1][lr] = av.y; As[lc+2][lr] = av.z; As[lc+3][lr] = av.w;
        Bs[lc+0][lr] = bv.x; Bs[lc+1][lr] = bv.y; Bs[lc+2][lr] = bv.z; Bs[lc+3][lr] = bv.w;
        __syncthreads();
#pragma unroll
        for (int k = 0; k < 8; k++) {
            float a[8], b[8];
            float4 t0 = *(const float4*)&As[k][ty*8];
            float4 t1 = *(const float4*)&As[k][ty*8 + 4];
            a[0]=t0.x; a[1]=t0.y; a[2]=t0.z; a[3]=t0.w;
            a[4]=t1.x; a[5]=t1.y; a[6]=t1.z; a[7]=t1.w;
            float4 s0 = *(const float4*)&Bs[k][tx*8];
            float4 s1 = *(const float4*)&Bs[k][tx*8 + 4];
            b[0]=s0.x; b[1]=s0.y; b[2]=s0.z; b[3]=s0.w;
            b[4]=s1.x; b[5]=s1.y; b[6]=s1.z; b[7]=s1.w;
#pragma unroll
            for (int i = 0; i < 8; i++)
#pragma unroll
                for (int j = 0; j < 8; j++)
                    acc[i][j] = fmaf(a[i], b[j], acc[i][j]);
        }
        __syncthreads();
    }

#pragma unroll
    for (int i = 0; i < 8; i++) {
        int r = brow + ty*8 + i;
        if (r >= M) continue;
#pragma unroll
        for (int j = 0; j < 8; j++) {
            int c = bcol + tx*8 + j;
            if (c >= N) continue;
            float v = acc[i][j];
            if (ep == 1) {
                v += bias[c];
                v = (v > 20.f) ? v : log1pf(__expf(v));   // softplus
            }
            C[(size_t)r*ldc + c] = v;
        }
    }
}

// ---------------- causal depthwise conv (width 4) + bias + silu -------------
__global__ __launch_bounds__(256)
void conv_silu_kernel(const float* __restrict__ xz,
                      const float* __restrict__ cw,
                      const float* __restrict__ cb,
                      float* __restrict__ u)
{
    int idx = blockIdx.x * 256 + threadIdx.x;        // row*DI + d
    if (idx >= BB*LL*DI) return;
    int d = idx & (DI - 1);
    int t = (idx >> 11) & (LL - 1);
    size_t base = (size_t)(idx >> 11) * (2*DI) + d;  // xz row stride = 4096

    float w0 = cw[d*4+0], w1 = cw[d*4+1], w2 = cw[d*4+2], w3 = cw[d*4+3];
    float acc = cb[d];
    if (t >= 3) acc = fmaf(xz[base - 3*(size_t)(2*DI)], w0, acc);
    if (t >= 2) acc = fmaf(xz[base - 2*(size_t)(2*DI)], w1, acc);
    if (t >= 1) acc = fmaf(xz[base -   (size_t)(2*DI)], w2, acc);
    acc = fmaf(xz[base], w3, acc);

    float sig = 1.f / (1.f + __expf(-acc));
    u[idx] = acc * sig;                               // silu
}

// ---------------- selective scan + skip + gate -------------------------------
// 16 lanes per (b,d) channel (one per state n); 2 channels per warp.
// Recurrence:  h = exp(dt*A[d,n])*h + (dt*u)*B_t[n];  y_t = sum_n h*C_t[n].
// Epilogue:    yg = (y_t + u*Dskip[d]) * silu(z).
__global__ __launch_bounds__(128)
void scan_kernel(const float* __restrict__ delta,
                 const float* __restrict__ u,
                 const float* __restrict__ xdbl,
                 const float* __restrict__ xz,
                 const float* __restrict__ A_log,
                 const float* __restrict__ Dskip,
                 float* __restrict__ yg)
{
    int gtid = blockIdx.x * 128 + threadIdx.x;
    int ch = gtid >> 4;            // 0..4095  (b*DI + d)
    int nq = gtid & 15;            // state index
    int b  = ch >> 11;
    int d  = ch & (DI - 1);

    const float An = -__expf(A_log[d*DS + nq]);
    const float Dd = Dskip[d];
    float h = 0.f;

    const size_t rbase = (size_t)b * LL;

    // software-pipelined operand loads (hide L1/L2 latency across the chain)
    size_t row = rbase;
    float dtv = delta[row*DI + d];
    float uv  = u    [row*DI + d];
    float Bn  = xdbl [row*XPC + DTR + nq];
    float Cn  = xdbl [row*XPC + DTR + DS + nq];
    float zv  = xz   [row*(2*DI) + DI + d];

    for (int t = 0; t < LL; t++) {
        float dtv2 = 0.f, uv2 = 0.f, Bn2 = 0.f, Cn2 = 0.f, zv2 = 0.f;
        if (t + 1 < LL) {
            size_t nrow = rbase + t + 1;
            dtv2 = delta[nrow*DI + d];
            uv2  = u    [nrow*DI + d];
            Bn2  = xdbl [nrow*XPC + DTR + nq];
            Cn2  = xdbl [nrow*XPC + DTR + DS + nq];
            zv2  = xz   [nrow*(2*DI) + DI + d];
        }

        float dA = __expf(dtv * An);
        h = fmaf(dA, h, (dtv * uv) * Bn);
        float yp = h * Cn;
        yp += __shfl_xor_sync(0xffffffffu, yp, 1);
        yp += __shfl_xor_sync(0xffffffffu, yp, 2);
        yp += __shfl_xor_sync(0xffffffffu, yp, 4);
        yp += __shfl_xor_sync(0xffffffffu, yp, 8);

        if (nq == 0) {
            float yfull = yp + uv * Dd;
            float sig = 1.f / (1.f + __expf(-zv));
            yg[(rbase + t)*DI + d] = yfull * (zv * sig);
        }
        dtv = dtv2; uv = uv2; Bn = Bn2; Cn = Cn2; zv = zv2;
    }
}

// ---------------- launch -----------------------------------------------------
extern "C" void kernel_launch(void* const* d_in, const int* in_sizes, int n_in,
                              void* d_out, int out_size)
{
    (void)in_sizes; (void)n_in; (void)out_size;
    const float* x       = (const float*)d_in[0];
    const float* W_in    = (const float*)d_in[1];
    const float* conv_w  = (const float*)d_in[2];
    const float* conv_b  = (const float*)d_in[3];
    const float* W_xproj = (const float*)d_in[4];
    const float* W_dt    = (const float*)d_in[5];
    const float* b_dt    = (const float*)d_in[6];
    const float* A_log   = (const float*)d_in[7];
    const float* Dskip   = (const float*)d_in[8];
    const float* W_out   = (const float*)d_in[9];
    float* out = (float*)d_out;

    float *xz, *u, *xdbl, *delta, *yg;
    cudaGetSymbolAddress((void**)&xz,    g_xz);
    cudaGetSymbolAddress((void**)&u,     g_u);
    cudaGetSymbolAddress((void**)&xdbl,  g_xdbl);
    cudaGetSymbolAddress((void**)&delta, g_delta);
    cudaGetSymbolAddress((void**)&yg,    g_yg);

    // 1) in_proj: xz[4096,4096] = x[4096,1024] @ W_in[4096,1024]^T
    gemm_nt_128<<<dim3(32, 32), 256>>>(x, DM, W_in, DM, xz, 2*DI,
                                       MROWS, 2*DI, DM, nullptr, 0);
    // 2) causal depthwise conv + silu -> u[4096,2048]
    conv_silu_kernel<<<(BB*LL*DI + 255)/256, 256>>>(xz, conv_w, conv_b, u);
    // 3) x_proj: xdbl[4096,96] = u @ W_xproj[96,2048]^T
    gemm_nt_128<<<dim3(1, 32), 256>>>(u, DI, W_xproj, DI, xdbl, XPC,
                                      MROWS, XPC, DI, nullptr, 0);
    // 4) delta[4096,2048] = softplus(dt_low @ W_dt^T + b_dt)   (dt_low = xdbl[:, :64])
    gemm_nt_128<<<dim3(16, 32), 256>>>(xdbl, XPC, W_dt, DTR, delta, DI,
                                       MROWS, DI, DTR, b_dt, 1);
    // 5) selective scan + skip + gate -> yg[4096,2048]
    scan_kernel<<<512, 128>>>(delta, u, xdbl, xz, A_log, Dskip, yg);
    // 6) out_proj: out[4096,1024] = yg @ W_out[1024,2048]^T
    gemm_nt_128<<<dim3(8, 32), 256>>>(yg, DI, W_out, DI, out, DM,
                                      MROWS, DM, DI, nullptr, 0);
}

// round 3
// speedup vs baseline: 1.6882x; 1.6882x over previous
#include <cuda_runtime.h>
#include <cuda_bf16.h>
#include <math.h>
#include <stdint.h>

#define BB   2
#define LL   2048
#define DM   1024
#define DI   2048
#define DS   16
#define DTR  64
#define MROWS (BB*LL)          /* 4096 */
#define XPC  (DTR + 2*DS)      /* 96   */

// ---------------- scratch (device globals; allocation-free) -----------------
__device__ float g_xz   [(size_t)MROWS * 2 * DI];   // 4096 x 4096 fp32 (xb | z)
__device__ float g_u    [(size_t)MROWS * DI];       // conv+silu fp32
__device__ float g_xdbl [(size_t)MROWS * XPC];      // fp32 dt_low | B | C
__device__ float g_delta[(size_t)MROWS * DI];       // softplus(dt) fp32

__device__ __nv_bfloat16 g_xhi [(size_t)MROWS * DM];
__device__ __nv_bfloat16 g_xlo [(size_t)MROWS * DM];
__device__ __nv_bfloat16 g_uhi [(size_t)MROWS * DI];
__device__ __nv_bfloat16 g_ulo [(size_t)MROWS * DI];
__device__ __nv_bfloat16 g_xdhi[(size_t)MROWS * XPC];
__device__ __nv_bfloat16 g_xdlo[(size_t)MROWS * XPC];
__device__ __nv_bfloat16 g_yghi[(size_t)MROWS * DI];
__device__ __nv_bfloat16 g_yglo[(size_t)MROWS * DI];
__device__ __nv_bfloat16 g_wih [(size_t)(2*DI) * DM];
__device__ __nv_bfloat16 g_wil [(size_t)(2*DI) * DM];
__device__ __nv_bfloat16 g_wxh [(size_t)XPC * DI];
__device__ __nv_bfloat16 g_wxl [(size_t)XPC * DI];
__device__ __nv_bfloat16 g_wdh [(size_t)DI * DTR];
__device__ __nv_bfloat16 g_wdl [(size_t)DI * DTR];
__device__ __nv_bfloat16 g_woh [(size_t)DM * DI];
__device__ __nv_bfloat16 g_wol [(size_t)DM * DI];

// ====================== helpers ==============================================
#define SW128(o) ((o) ^ (((o) >> 3) & 0x70))

__device__ __forceinline__ uint32_t smem_u32(const void* p) {
    uint32_t a;
    asm("{ .reg .u64 t; cvta.to.shared.u64 t, %1; cvt.u32.u64 %0, t; }"
        : "=r"(a) : "l"(p));
    return a;
}
__device__ __forceinline__ void cp16(uint32_t s, const void* g) {
    asm volatile("cp.async.cg.shared.global [%0], [%1], 16;"
                 :: "r"(s), "l"(g) : "memory");
}
#define CP_COMMIT()  asm volatile("cp.async.commit_group;" ::: "memory")
#define CP_WAIT(n)   asm volatile("cp.async.wait_group %0;" :: "n"(n) : "memory")

__device__ __forceinline__ void ldsm_x4(uint32_t* r, uint32_t addr) {
    asm volatile("ldmatrix.sync.aligned.m8n8.x4.shared.b16 {%0,%1,%2,%3}, [%4];"
        : "=r"(r[0]), "=r"(r[1]), "=r"(r[2]), "=r"(r[3]) : "r"(addr));
}
__device__ __forceinline__ void mma16816(float* d, const uint32_t* a, const uint32_t* b) {
    asm volatile("mma.sync.aligned.m16n8k16.row.col.f32.bf16.bf16.f32 "
        "{%0,%1,%2,%3}, {%4,%5,%6,%7}, {%8,%9}, {%0,%1,%2,%3};"
        : "+f"(d[0]), "+f"(d[1]), "+f"(d[2]), "+f"(d[3])
        : "r"(a[0]), "r"(a[1]), "r"(a[2]), "r"(a[3]), "r"(b[0]), "r"(b[1]));
}

// ====================== split fp32 -> bf16 hi/lo =============================
__global__ __launch_bounds__(256)
void split_f32(const float* __restrict__ s, __nv_bfloat16* __restrict__ hi,
               __nv_bfloat16* __restrict__ lo, int n4)
{
    int i = blockIdx.x * 256 + threadIdx.x;
    if (i >= n4) return;
    float4 v = ((const float4*)s)[i];
    __nv_bfloat16 h0 = __float2bfloat16(v.x), h1 = __float2bfloat16(v.y);
    __nv_bfloat16 h2 = __float2bfloat16(v.z), h3 = __float2bfloat16(v.w);
    __nv_bfloat162 H0; H0.x = h0; H0.y = h1;
    __nv_bfloat162 H1; H1.x = h2; H1.y = h3;
    ((__nv_bfloat162*)hi)[i*2+0] = H0;
    ((__nv_bfloat162*)hi)[i*2+1] = H1;
    __nv_bfloat162 L0, L1;
    L0.x = __float2bfloat16(v.x - __bfloat162float(h0));
    L0.y = __float2bfloat16(v.y - __bfloat162float(h1));
    L1.x = __float2bfloat16(v.z - __bfloat162float(h2));
    L1.y = __float2bfloat16(v.w - __bfloat162float(h3));
    ((__nv_bfloat162*)lo)[i*2+0] = L0;
    ((__nv_bfloat162*)lo)[i*2+1] = L1;
}

// ====================== split-bf16 HMMA GEMM =================================
// C[M,N] = (Ah+Al)[M,K] * (Bh+Bl)[N,K]^T   (3 K-segments: AhBh, AlBh, AhBl)
// CTA 128x128, BK=64 bf16, 256 threads (8 warps: 4 m-rows x 2 n-cols),
// double-buffered cp.async, SW128 swizzle, ldmatrix.x4 frags.
// ep=0: fp32 C.  ep=1: C = softplus(acc+bias[col]).  ep=2: fp32 C + bf16 split.
#define SMEM_DYN (64*1024 + 1024)

__global__ __launch_bounds__(256)
void mma_gemm(const __nv_bfloat16* __restrict__ Ah, const __nv_bfloat16* __restrict__ Al, int lda,
              const __nv_bfloat16* __restrict__ Bh, const __nv_bfloat16* __restrict__ Bl, int ldb,
              float* __restrict__ C, int ldc, int N, int K64,
              const float* __restrict__ bias, int ep,
              __nv_bfloat16* __restrict__ Chi, __nv_bfloat16* __restrict__ Clo)
{
    extern __shared__ char dsm[];

    const int tid = threadIdx.x;
    const int wid = tid >> 5;
    const int lid = tid & 31;
    const int brow = blockIdx.y * 128;
    const int bcol = blockIdx.x * 128;

    uint32_t sbase = (smem_u32(dsm) + 1023) & ~1023u;
    const uint32_t sA[2] = { sbase,         sbase + 32768 };
    const uint32_t sB[2] = { sbase + 16384, sbase + 49152 };

    const int KT = 3 * K64;

    // warp tile: 32 rows x 64 cols
    const int mbase = (wid >> 1) * 32;
    const int nbase = (wid & 1) * 64;

    float acc[2][8][4];
#pragma unroll
    for (int i = 0; i < 2; i++)
#pragma unroll
        for (int j = 0; j < 8; j++)
#pragma unroll
            for (int k = 0; k < 4; k++) acc[i][j][k] = 0.f;

    // --- tile loader: tile j -> buffer (j&1). 128 rows x 128B per operand. ---
    auto load_tile = [&](int j) {
        int s  = j / K64;
        int kb = (j - s * K64) << 6;          // element offset (64 per tile)
        const __nv_bfloat16* Ap = (s == 1) ? Al : Ah;
        const __nv_bfloat16* Bp = (s == 2) ? Bl : Bh;
        uint32_t sa = sA[j & 1];
        uint32_t sb = sB[j & 1];
#pragma unroll
        for (int it = 0; it < 4; it++) {
            int slot = tid + it * 256;
            int rr = slot >> 3, ch = slot & 7;
            uint32_t off = SW128(rr * 128 + ch * 16);
            cp16(sa + off, Ap + (size_t)(brow + rr) * lda + kb + ch * 8);
        }
#pragma unroll
        for (int it = 0; it < 4; it++) {
            int slot = tid + it * 256;
            int rr = slot >> 3, ch = slot & 7;
            uint32_t off = SW128(rr * 128 + ch * 16);
            if (bcol + rr < N) {
                cp16(sb + off, Bp + (size_t)(bcol + rr) * ldb + kb + ch * 8);
            } else {
                asm volatile("st.shared.v4.b32 [%0], {%1, %1, %1, %1};"
                             :: "r"(sb + off), "r"(0) : "memory");
            }
        }
    };

    load_tile(0); CP_COMMIT();

    for (int kt = 0; kt < KT; kt++) {
        if (kt + 1 < KT) { load_tile(kt + 1); CP_COMMIT(); CP_WAIT(1); }
        else             { CP_WAIT(0); }
        __syncthreads();

        uint32_t sa = sA[kt & 1], sb = sB[kt & 1];
#pragma unroll
        for (int ks = 0; ks < 4; ks++) {
            uint32_t a[2][4], b[4][4];
#pragma unroll
            for (int mt = 0; mt < 2; mt++) {
                int row = mbase + mt * 16 + (lid & 15);
                int kb  = ks * 32 + ((lid >> 4) << 4);
                ldsm_x4(a[mt], sa + SW128(row * 128 + kb));
            }
#pragma unroll
            for (int bp = 0; bp < 4; bp++) {
                int nr = nbase + bp * 16 + (lid & 7) + ((lid >> 4) << 3);
                int kb = ks * 32 + (((lid >> 3) & 1) << 4);
                ldsm_x4(b[bp], sb + SW128(nr * 128 + kb));
            }
#pragma unroll
            for (int mt = 0; mt < 2; mt++)
#pragma unroll
                for (int nt = 0; nt < 8; nt++)
                    mma16816(acc[mt][nt], a[mt], &b[nt >> 1][(nt & 1) * 2]);
        }
        __syncthreads();
    }

    // --- epilogue: register accumulators -> global ---
#pragma unroll
    for (int mt = 0; mt < 2; mt++) {
#pragma unroll
        for (int nt = 0; nt < 8; nt++) {
            int c = bcol + nbase + nt * 8 + (lid & 3) * 2;
            if (c >= N) continue;
#pragma unroll
            for (int half = 0; half < 2; half++) {
                int r = brow + mbase + mt * 16 + (lid >> 2) + half * 8;
                float v0 = acc[mt][nt][half * 2 + 0];
                float v1 = acc[mt][nt][half * 2 + 1];
                if (ep == 1) {
                    v0 += bias[c];
                    v1 += bias[c + 1];
                    v0 = (v0 > 20.f) ? v0 : log1pf(__expf(v0));
                    v1 = (v1 > 20.f) ? v1 : log1pf(__expf(v1));
                }
                size_t o = (size_t)r * ldc + c;
                *(float2*)&C[o] = make_float2(v0, v1);
                if (ep == 2) {
                    __nv_bfloat16 h0 = __float2bfloat16(v0);
                    __nv_bfloat16 h1 = __float2bfloat16(v1);
                    __nv_bfloat162 H; H.x = h0; H.y = h1;
                    *(__nv_bfloat162*)&Chi[o] = H;
                    __nv_bfloat162 Lo;
                    Lo.x = __float2bfloat16(v0 - __bfloat162float(h0));
                    Lo.y = __float2bfloat16(v1 - __bfloat162float(h1));
                    *(__nv_bfloat162*)&Clo[o] = Lo;
                }
            }
        }
    }
}

// ---------------- causal depthwise conv (width 4) + bias + silu -------------
__global__ __launch_bounds__(256)
void conv_silu_kernel(const float* __restrict__ xz,
                      const float* __restrict__ cw,
                      const float* __restrict__ cb,
                      float* __restrict__ u,
                      __nv_bfloat16* __restrict__ uhi,
                      __nv_bfloat16* __restrict__ ulo)
{
    int idx = blockIdx.x * 256 + threadIdx.x;
    if (idx >= BB*LL*DI) return;
    int d = idx & (DI - 1);
    int t = (idx >> 11) & (LL - 1);
    size_t base = (size_t)(idx >> 11) * (2*DI) + d;

    float w0 = cw[d*4+0], w1 = cw[d*4+1], w2 = cw[d*4+2], w3 = cw[d*4+3];
    float acc = cb[d];
    if (t >= 3) acc = fmaf(xz[base - 3*(size_t)(2*DI)], w0, acc);
    if (t >= 2) acc = fmaf(xz[base - 2*(size_t)(2*DI)], w1, acc);
    if (t >= 1) acc = fmaf(xz[base -   (size_t)(2*DI)], w2, acc);
    acc = fmaf(xz[base], w3, acc);

    float sig = 1.f / (1.f + __expf(-acc));
    float v = acc * sig;
    u[idx] = v;
    __nv_bfloat16 h = __float2bfloat16(v);
    uhi[idx] = h;
    ulo[idx] = __float2bfloat16(v - __bfloat162float(h));
}

// ---------------- selective scan + skip + gate -------------------------------
__global__ __launch_bounds__(128)
void scan_kernel(const float* __restrict__ delta,
                 const float* __restrict__ u,
                 const float* __restrict__ xdbl,
                 const float* __restrict__ xz,
                 const float* __restrict__ A_log,
                 const float* __restrict__ Dskip,
                 __nv_bfloat16* __restrict__ yghi,
                 __nv_bfloat16* __restrict__ yglo)
{
    int gtid = blockIdx.x * 128 + threadIdx.x;
    int ch = gtid >> 4;
    int nq = gtid & 15;
    int b  = ch >> 11;
    int d  = ch & (DI - 1);

    const float An = -__expf(A_log[d*DS + nq]);
    const float Dd = Dskip[d];
    float h = 0.f;

    const size_t rbase = (size_t)b * LL;

    float dtv = delta[rbase*DI + d];
    float uv  = u    [rbase*DI + d];
    float Bn  = xdbl [rbase*XPC + DTR + nq];
    float Cn  = xdbl [rbase*XPC + DTR + DS + nq];
    float zv  = xz   [rbase*(2*DI) + DI + d];

    for (int t = 0; t < LL; t++) {
        float dtv2 = 0.f, uv2 = 0.f, Bn2 = 0.f, Cn2 = 0.f, zv2 = 0.f;
        if (t + 1 < LL) {
            size_t nrow = rbase + t + 1;
            dtv2 = delta[nrow*DI + d];
            uv2  = u    [nrow*DI + d];
            Bn2  = xdbl [nrow*XPC + DTR + nq];
            Cn2  = xdbl [nrow*XPC + DTR + DS + nq];
            zv2  = xz   [nrow*(2*DI) + DI + d];
        }

        float dA = __expf(dtv * An);
        h = fmaf(dA, h, (dtv * uv) * Bn);
        float yp = h * Cn;
        yp += __shfl_xor_sync(0xffffffffu, yp, 1);
        yp += __shfl_xor_sync(0xffffffffu, yp, 2);
        yp += __shfl_xor_sync(0xffffffffu, yp, 4);
        yp += __shfl_xor_sync(0xffffffffu, yp, 8);

        if (nq == 0) {
            float yfull = yp + uv * Dd;
            float sig = 1.f / (1.f + __expf(-zv));
            float g = yfull * (zv * sig);
            size_t o = (rbase + t)*DI + d;
            __nv_bfloat16 hh = __float2bfloat16(g);
            yghi[o] = hh;
            yglo[o] = __float2bfloat16(g - __bfloat162float(hh));
        }
        dtv = dtv2; uv = uv2; Bn = Bn2; Cn = Cn2; zv = zv2;
    }
}

// ---------------- launch -----------------------------------------------------
extern "C" void kernel_launch(void* const* d_in, const int* in_sizes, int n_in,
                              void* d_out, int out_size)
{
    (void)in_sizes; (void)n_in; (void)out_size;
    const float* x       = (const float*)d_in[0];
    const float* W_in    = (const float*)d_in[1];
    const float* conv_w  = (const float*)d_in[2];
    const float* conv_b  = (const float*)d_in[3];
    const float* W_xproj = (const float*)d_in[4];
    const float* W_dt    = (const float*)d_in[5];
    const float* b_dt    = (const float*)d_in[6];
    const float* A_log   = (const float*)d_in[7];
    const float* Dskip   = (const float*)d_in[8];
    const float* W_out   = (const float*)d_in[9];
    float* out = (float*)d_out;

    float *xz, *u, *xdbl, *delta;
    __nv_bfloat16 *xhi, *xlo, *uhi, *ulo, *xdhi, *xdlo, *yghi, *yglo;
    __nv_bfloat16 *wih, *wil, *wxh, *wxl, *wdh, *wdl, *woh, *wol;
    cudaGetSymbolAddress((void**)&xz,    g_xz);
    cudaGetSymbolAddress((void**)&u,     g_u);
    cudaGetSymbolAddress((void**)&xdbl,  g_xdbl);
    cudaGetSymbolAddress((void**)&delta, g_delta);
    cudaGetSymbolAddress((void**)&xhi,   g_xhi);
    cudaGetSymbolAddress((void**)&xlo,   g_xlo);
    cudaGetSymbolAddress((void**)&uhi,   g_uhi);
    cudaGetSymbolAddress((void**)&ulo,   g_ulo);
    cudaGetSymbolAddress((void**)&xdhi,  g_xdhi);
    cudaGetSymbolAddress((void**)&xdlo,  g_xdlo);
    cudaGetSymbolAddress((void**)&yghi,  g_yghi);
    cudaGetSymbolAddress((void**)&yglo,  g_yglo);
    cudaGetSymbolAddress((void**)&wih,   g_wih);
    cudaGetSymbolAddress((void**)&wil,   g_wil);
    cudaGetSymbolAddress((void**)&wxh,   g_wxh);
    cudaGetSymbolAddress((void**)&wxl,   g_wxl);
    cudaGetSymbolAddress((void**)&wdh,   g_wdh);
    cudaGetSymbolAddress((void**)&wdl,   g_wdl);
    cudaGetSymbolAddress((void**)&woh,   g_woh);
    cudaGetSymbolAddress((void**)&wol,   g_wol);

    cudaFuncSetAttribute(mma_gemm, cudaFuncAttributeMaxDynamicSharedMemorySize, SMEM_DYN);

    // bf16 splits of inputs/weights
    split_f32<<<(MROWS*DM/4 + 255)/256, 256>>>(x,       xhi, xlo, MROWS*DM/4);
    split_f32<<<(2*DI*DM/4  + 255)/256, 256>>>(W_in,    wih, wil, 2*DI*DM/4);
    split_f32<<<(XPC*DI/4   + 255)/256, 256>>>(W_xproj, wxh, wxl, XPC*DI/4);
    split_f32<<<(DI*DTR/4   + 255)/256, 256>>>(W_dt,    wdh, wdl, DI*DTR/4);
    split_f32<<<(DM*DI/4    + 255)/256, 256>>>(W_out,   woh, wol, DM*DI/4);

    // 1) in_proj: xz[4096,4096] = x @ W_in^T
    mma_gemm<<<dim3(32, 32), 256, SMEM_DYN>>>(xhi, xlo, DM, wih, wil, DM,
                                              xz, 2*DI, 2*DI, DM/64,
                                              nullptr, 0, nullptr, nullptr);
    // 2) conv + silu -> u (fp32 + bf16 split)
    conv_silu_kernel<<<(BB*LL*DI + 255)/256, 256>>>(xz, conv_w, conv_b, u, uhi, ulo);
    // 3) x_proj: xdbl[4096,96] = u @ W_xproj^T  (fp32 + bf16 split)
    mma_gemm<<<dim3(1, 32), 256, SMEM_DYN>>>(uhi, ulo, DI, wxh, wxl, DI,
                                             xdbl, XPC, XPC, DI/64,
                                             nullptr, 2, xdhi, xdlo);
    // 4) delta = softplus(dt_low @ W_dt^T + b_dt)
    mma_gemm<<<dim3(16, 32), 256, SMEM_DYN>>>(xdhi, xdlo, XPC, wdh, wdl, DTR,
                                              delta, DI, DI, DTR/64,
                                              b_dt, 1, nullptr, nullptr);
    // 5) selective scan + skip + gate -> yg (bf16 split)
    scan_kernel<<<512, 128>>>(delta, u, xdbl, xz, A_log, Dskip, yghi, yglo);
    // 6) out_proj: out[4096,1024] = yg @ W_out^T
    mma_gemm<<<dim3(8, 32), 256, SMEM_DYN>>>(yghi, yglo, DI, woh, wol, DI,
                                             out, DM, DM, DI/64,
                                             nullptr, 0, nullptr, nullptr);
}

// round 4
// speedup vs baseline: 1.7053x; 1.0101x over previous
#include <cuda_runtime.h>
#include <cuda_bf16.h>
#include <math.h>
#include <stdint.h>

#define BB   2
#define LL   2048
#define DM   1024
#define DI   2048
#define DS   16
#define DTR  64
#define MROWS (BB*LL)          /* 4096 */
#define XPC  (DTR + 2*DS)      /* 96   */

// ---------------- scratch (device globals; allocation-free) -----------------
__device__ float g_xz   [(size_t)MROWS * 2 * DI];   // 4096 x 4096 fp32 (xb | z)
__device__ float g_u    [(size_t)MROWS * DI];       // conv+silu fp32
__device__ float g_xdbl [(size_t)MROWS * XPC];      // fp32 dt_low | B | C
__device__ float g_delta[(size_t)MROWS * DI];       // softplus(dt) fp32

__device__ __nv_bfloat16 g_xhi [(size_t)MROWS * DM];
__device__ __nv_bfloat16 g_xlo [(size_t)MROWS * DM];
__device__ __nv_bfloat16 g_uhi [(size_t)MROWS * DI];
__device__ __nv_bfloat16 g_ulo [(size_t)MROWS * DI];
__device__ __nv_bfloat16 g_xdhi[(size_t)MROWS * XPC];
__device__ __nv_bfloat16 g_xdlo[(size_t)MROWS * XPC];
__device__ __nv_bfloat16 g_yghi[(size_t)MROWS * DI];
__device__ __nv_bfloat16 g_yglo[(size_t)MROWS * DI];
__device__ __nv_bfloat16 g_wih [(size_t)(2*DI) * DM];
__device__ __nv_bfloat16 g_wil [(size_t)(2*DI) * DM];
__device__ __nv_bfloat16 g_wxh [(size_t)XPC * DI];
__device__ __nv_bfloat16 g_wxl [(size_t)XPC * DI];
__device__ __nv_bfloat16 g_wdh [(size_t)DI * DTR];
__device__ __nv_bfloat16 g_wdl [(size_t)DI * DTR];
__device__ __nv_bfloat16 g_woh [(size_t)DM * DI];
__device__ __nv_bfloat16 g_wol [(size_t)DM * DI];

// ====================== helpers ==============================================
#define SW128(o) ((o) ^ (((o) >> 3) & 0x70))

__device__ __forceinline__ uint32_t smem_u32(const void* p) {
    uint32_t a;
    asm("{ .reg .u64 t; cvta.to.shared.u64 t, %1; cvt.u32.u64 %0, t; }"
        : "=r"(a) : "l"(p));
    return a;
}
__device__ __forceinline__ void cp16(uint32_t s, const void* g) {
    asm volatile("cp.async.cg.shared.global [%0], [%1], 16;"
                 :: "r"(s), "l"(g) : "memory");
}
#define CP_COMMIT()  asm volatile("cp.async.commit_group;" ::: "memory")
#define CP_WAIT(n)   asm volatile("cp.async.wait_group %0;" :: "n"(n) : "memory")

__device__ __forceinline__ void ldsm_x4(uint32_t* r, uint32_t addr) {
    asm volatile("ldmatrix.sync.aligned.m8n8.x4.shared.b16 {%0,%1,%2,%3}, [%4];"
        : "=r"(r[0]), "=r"(r[1]), "=r"(r[2]), "=r"(r[3]) : "r"(addr));
}
__device__ __forceinline__ void mma16816(float* d, const uint32_t* a, const uint32_t* b) {
    asm volatile("mma.sync.aligned.m16n8k16.row.col.f32.bf16.bf16.f32 "
        "{%0,%1,%2,%3}, {%4,%5,%6,%7}, {%8,%9}, {%0,%1,%2,%3};"
        : "+f"(d[0]), "+f"(d[1]), "+f"(d[2]), "+f"(d[3])
        : "r"(a[0]), "r"(a[1]), "r"(a[2]), "r"(a[3]), "r"(b[0]), "r"(b[1]));
}

// ====================== split fp32 -> bf16 hi/lo =============================
__global__ __launch_bounds__(256)
void split_f32(const float* __restrict__ s, __nv_bfloat16* __restrict__ hi,
               __nv_bfloat16* __restrict__ lo, int n4)
{
    int i = blockIdx.x * 256 + threadIdx.x;
    if (i >= n4) return;
    float4 v = ((const float4*)s)[i];
    __nv_bfloat16 h0 = __float2bfloat16(v.x), h1 = __float2bfloat16(v.y);
    __nv_bfloat16 h2 = __float2bfloat16(v.z), h3 = __float2bfloat16(v.w);
    __nv_bfloat162 H0; H0.x = h0; H0.y = h1;
    __nv_bfloat162 H1; H1.x = h2; H1.y = h3;
    ((__nv_bfloat162*)hi)[i*2+0] = H0;
    ((__nv_bfloat162*)hi)[i*2+1] = H1;
    __nv_bfloat162 L0, L1;
    L0.x = __float2bfloat16(v.x - __bfloat162float(h0));
    L0.y = __float2bfloat16(v.y - __bfloat162float(h1));
    L1.x = __float2bfloat16(v.z - __bfloat162float(h2));
    L1.y = __float2bfloat16(v.w - __bfloat162float(h3));
    ((__nv_bfloat162*)lo)[i*2+0] = L0;
    ((__nv_bfloat162*)lo)[i*2+1] = L1;
}

// ====================== split-bf16 HMMA GEMM =================================
// C[M,N] = (Ah+Al)[M,K] * (Bh+Bl)[N,K]^T   (3 K-segments: AhBh, AlBh, AhBl)
// CTA 128x128, BK=64 bf16, 256 threads (8 warps: 4 m-rows x 2 n-cols),
// 3-stage cp.async pipeline (ONE __syncthreads per K-tile), SW128 swizzle.
// ep=0: fp32 C.  ep=1: C = softplus(acc+bias[col]).  ep=2: fp32 C + bf16 split.
#define NSTAGE 3
#define SMEM_DYN (NSTAGE*32*1024 + 1024)

__global__ __launch_bounds__(256, 2)
void mma_gemm(const __nv_bfloat16* __restrict__ Ah, const __nv_bfloat16* __restrict__ Al, int lda,
              const __nv_bfloat16* __restrict__ Bh, const __nv_bfloat16* __restrict__ Bl, int ldb,
              float* __restrict__ C, int ldc, int N, int K64,
              const float* __restrict__ bias, int ep,
              __nv_bfloat16* __restrict__ Chi, __nv_bfloat16* __restrict__ Clo)
{
    extern __shared__ char dsm[];

    const int tid = threadIdx.x;
    const int wid = tid >> 5;
    const int lid = tid & 31;
    const int brow = blockIdx.y * 128;
    const int bcol = blockIdx.x * 128;

    uint32_t sbase = (smem_u32(dsm) + 1023) & ~1023u;
    uint32_t sA[NSTAGE], sB[NSTAGE];
#pragma unroll
    for (int s = 0; s < NSTAGE; s++) {
        sA[s] = sbase + s * 32768;
        sB[s] = sbase + s * 32768 + 16384;
    }

    const int KT = 3 * K64;

    // warp tile: 32 rows x 64 cols
    const int mbase = (wid >> 1) * 32;
    const int nbase = (wid & 1) * 64;

    float acc[2][8][4];
#pragma unroll
    for (int i = 0; i < 2; i++)
#pragma unroll
        for (int j = 0; j < 8; j++)
#pragma unroll
            for (int k = 0; k < 4; k++) acc[i][j][k] = 0.f;

    // --- tile loader: tile j -> stage (j % NSTAGE). 128 rows x 128B/operand. ---
    auto load_tile = [&](int j) {
        int s  = j / K64;
        int kb = (j - s * K64) << 6;          // element offset (64 per tile)
        const __nv_bfloat16* Ap = (s == 1) ? Al : Ah;
        const __nv_bfloat16* Bp = (s == 2) ? Bl : Bh;
        int st = j % NSTAGE;
        uint32_t sa = sA[st];
        uint32_t sb = sB[st];
#pragma unroll
        for (int it = 0; it < 4; it++) {
            int slot = tid + it * 256;
            int rr = slot >> 3, ch = slot & 7;
            uint32_t off = SW128(rr * 128 + ch * 16);
            cp16(sa + off, Ap + (size_t)(brow + rr) * lda + kb + ch * 8);
        }
#pragma unroll
        for (int it = 0; it < 4; it++) {
            int slot = tid + it * 256;
            int rr = slot >> 3, ch = slot & 7;
            uint32_t off = SW128(rr * 128 + ch * 16);
            if (bcol + rr < N) {
                cp16(sb + off, Bp + (size_t)(bcol + rr) * ldb + kb + ch * 8);
            } else {
                asm volatile("st.shared.v4.b32 [%0], {%1, %1, %1, %1};"
                             :: "r"(sb + off), "r"(0) : "memory");
            }
        }
    };

    // prologue: stages 0 and 1 in flight
    load_tile(0); CP_COMMIT();
    if (KT > 1) { load_tile(1); CP_COMMIT(); }

    for (int kt = 0; kt < KT; kt++) {
        if (kt + 1 < KT) { CP_WAIT(1); }   // tile kt complete; kt+1 may fly
        else             { CP_WAIT(0); }
        __syncthreads();                    // single barrier per K-tile:
                                            // also protects stage (kt-1)%3,
                                            // which load_tile(kt+2) overwrites
        if (kt + 2 < KT) { load_tile(kt + 2); CP_COMMIT(); }

        uint32_t sa = sA[kt % NSTAGE], sb = sB[kt % NSTAGE];
#pragma unroll
        for (int ks = 0; ks < 4; ks++) {
            uint32_t a[2][4], b[4][4];
#pragma unroll
            for (int mt = 0; mt < 2; mt++) {
                int row = mbase + mt * 16 + (lid & 15);
                int kb  = ks * 32 + ((lid >> 4) << 4);
                ldsm_x4(a[mt], sa + SW128(row * 128 + kb));
            }
#pragma unroll
            for (int bp = 0; bp < 4; bp++) {
                int nr = nbase + bp * 16 + (lid & 7) + ((lid >> 4) << 3);
                int kb = ks * 32 + (((lid >> 3) & 1) << 4);
                ldsm_x4(b[bp], sb + SW128(nr * 128 + kb));
            }
#pragma unroll
            for (int mt = 0; mt < 2; mt++)
#pragma unroll
                for (int nt = 0; nt < 8; nt++)
                    mma16816(acc[mt][nt], a[mt], &b[nt >> 1][(nt & 1) * 2]);
        }
    }

    // --- epilogue: register accumulators -> global ---
#pragma unroll
    for (int mt = 0; mt < 2; mt++) {
#pragma unroll
        for (int nt = 0; nt < 8; nt++) {
            int c = bcol + nbase + nt * 8 + (lid & 3) * 2;
            if (c >= N) continue;
#pragma unroll
            for (int half = 0; half < 2; half++) {
                int r = brow + mbase + mt * 16 + (lid >> 2) + half * 8;
                float v0 = acc[mt][nt][half * 2 + 0];
                float v1 = acc[mt][nt][half * 2 + 1];
                if (ep == 1) {
                    v0 += bias[c];
                    v1 += bias[c + 1];
                    v0 = (v0 > 20.f) ? v0 : log1pf(__expf(v0));
                    v1 = (v1 > 20.f) ? v1 : log1pf(__expf(v1));
                }
                size_t o = (size_t)r * ldc + c;
                *(float2*)&C[o] = make_float2(v0, v1);
                if (ep == 2) {
                    __nv_bfloat16 h0 = __float2bfloat16(v0);
                    __nv_bfloat16 h1 = __float2bfloat16(v1);
                    __nv_bfloat162 H; H.x = h0; H.y = h1;
                    *(__nv_bfloat162*)&Chi[o] = H;
                    __nv_bfloat162 Lo;
                    Lo.x = __float2bfloat16(v0 - __bfloat162float(h0));
                    Lo.y = __float2bfloat16(v1 - __bfloat162float(h1));
                    *(__nv_bfloat162*)&Clo[o] = Lo;
                }
            }
        }
    }
}

// ---------------- causal depthwise conv (width 4) + bias + silu -------------
__global__ __launch_bounds__(256)
void conv_silu_kernel(const float* __restrict__ xz,
                      const float* __restrict__ cw,
                      const float* __restrict__ cb,
                      float* __restrict__ u,
                      __nv_bfloat16* __restrict__ uhi,
                      __nv_bfloat16* __restrict__ ulo)
{
    int idx = blockIdx.x * 256 + threadIdx.x;
    if (idx >= BB*LL*DI) return;
    int d = idx & (DI - 1);
    int t = (idx >> 11) & (LL - 1);
    size_t base = (size_t)(idx >> 11) * (2*DI) + d;

    float w0 = cw[d*4+0], w1 = cw[d*4+1], w2 = cw[d*4+2], w3 = cw[d*4+3];
    float acc = cb[d];
    if (t >= 3) acc = fmaf(xz[base - 3*(size_t)(2*DI)], w0, acc);
    if (t >= 2) acc = fmaf(xz[base - 2*(size_t)(2*DI)], w1, acc);
    if (t >= 1) acc = fmaf(xz[base -   (size_t)(2*DI)], w2, acc);
    acc = fmaf(xz[base], w3, acc);

    float sig = 1.f / (1.f + __expf(-acc));
    float v = acc * sig;
    u[idx] = v;
    __nv_bfloat16 h = __float2bfloat16(v);
    uhi[idx] = h;
    ulo[idx] = __float2bfloat16(v - __bfloat162float(h));
}

// ---------------- selective scan + skip + gate -------------------------------
__global__ __launch_bounds__(128)
void scan_kernel(const float* __restrict__ delta,
                 const float* __restrict__ u,
                 const float* __restrict__ xdbl,
                 const float* __restrict__ xz,
                 const float* __restrict__ A_log,
                 const float* __restrict__ Dskip,
                 __nv_bfloat16* __restrict__ yghi,
                 __nv_bfloat16* __restrict__ yglo)
{
    int gtid = blockIdx.x * 128 + threadIdx.x;
    int ch = gtid >> 4;
    int nq = gtid & 15;
    int b  = ch >> 11;
    int d  = ch & (DI - 1);

    const float An = -__expf(A_log[d*DS + nq]);
    const float Dd = Dskip[d];
    float h = 0.f;

    const size_t rbase = (size_t)b * LL;

    float dtv = delta[rbase*DI + d];
    float uv  = u    [rbase*DI + d];
    float Bn  = xdbl [rbase*XPC + DTR + nq];
    float Cn  = xdbl [rbase*XPC + DTR + DS + nq];
    float zv  = xz   [rbase*(2*DI) + DI + d];

    for (int t = 0; t < LL; t++) {
        float dtv2 = 0.f, uv2 = 0.f, Bn2 = 0.f, Cn2 = 0.f, zv2 = 0.f;
        if (t + 1 < LL) {
            size_t nrow = rbase + t + 1;
            dtv2 = delta[nrow*DI + d];
            uv2  = u    [nrow*DI + d];
            Bn2  = xdbl [nrow*XPC + DTR + nq];
            Cn2  = xdbl [nrow*XPC + DTR + DS + nq];
            zv2  = xz   [nrow*(2*DI) + DI + d];
        }

        float dA = __expf(dtv * An);
        h = fmaf(dA, h, (dtv * uv) * Bn);
        float yp = h * Cn;
        yp += __shfl_xor_sync(0xffffffffu, yp, 1);
        yp += __shfl_xor_sync(0xffffffffu, yp, 2);
        yp += __shfl_xor_sync(0xffffffffu, yp, 4);
        yp += __shfl_xor_sync(0xffffffffu, yp, 8);

        if (nq == 0) {
            float yfull = yp + uv * Dd;
            float sig = 1.f / (1.f + __expf(-zv));
            float g = yfull * (zv * sig);
            size_t o = (rbase + t)*DI + d;
            __nv_bfloat16 hh = __float2bfloat16(g);
            yghi[o] = hh;
            yglo[o] = __float2bfloat16(g - __bfloat162float(hh));
        }
        dtv = dtv2; uv = uv2; Bn = Bn2; Cn = Cn2; zv = zv2;
    }
}

// ---------------- launch -----------------------------------------------------
extern "C" void kernel_launch(void* const* d_in, const int* in_sizes, int n_in,
                              void* d_out, int out_size)
{
    (void)in_sizes; (void)n_in; (void)out_size;
    const float* x       = (const float*)d_in[0];
    const float* W_in    = (const float*)d_in[1];
    const float* conv_w  = (const float*)d_in[2];
    const float* conv_b  = (const float*)d_in[3];
    const float* W_xproj = (const float*)d_in[4];
    const float* W_dt    = (const float*)d_in[5];
    const float* b_dt    = (const float*)d_in[6];
    const float* A_log   = (const float*)d_in[7];
    const float* Dskip   = (const float*)d_in[8];
    const float* W_out   = (const float*)d_in[9];
    float* out = (float*)d_out;

    float *xz, *u, *xdbl, *delta;
    __nv_bfloat16 *xhi, *xlo, *uhi, *ulo, *xdhi, *xdlo, *yghi, *yglo;
    __nv_bfloat16 *wih, *wil, *wxh, *wxl, *wdh, *wdl, *woh, *wol;
    cudaGetSymbolAddress((void**)&xz,    g_xz);
    cudaGetSymbolAddress((void**)&u,     g_u);
    cudaGetSymbolAddress((void**)&xdbl,  g_xdbl);
    cudaGetSymbolAddress((void**)&delta, g_delta);
    cudaGetSymbolAddress((void**)&xhi,   g_xhi);
    cudaGetSymbolAddress((void**)&xlo,   g_xlo);
    cudaGetSymbolAddress((void**)&uhi,   g_uhi);
    cudaGetSymbolAddress((void**)&ulo,   g_ulo);
    cudaGetSymbolAddress((void**)&xdhi,  g_xdhi);
    cudaGetSymbolAddress((void**)&xdlo,  g_xdlo);
    cudaGetSymbolAddress((void**)&yghi,  g_yghi);
    cudaGetSymbolAddress((void**)&yglo,  g_yglo);
    cudaGetSymbolAddress((void**)&wih,   g_wih);
    cudaGetSymbolAddress((void**)&wil,   g_wil);
    cudaGetSymbolAddress((void**)&wxh,   g_wxh);
    cudaGetSymbolAddress((void**)&wxl,   g_wxl);
    cudaGetSymbolAddress((void**)&wdh,   g_wdh);
    cudaGetSymbolAddress((void**)&wdl,   g_wdl);
    cudaGetSymbolAddress((void**)&woh,   g_woh);
    cudaGetSymbolAddress((void**)&wol,   g_wol);

    cudaFuncSetAttribute(mma_gemm, cudaFuncAttributeMaxDynamicSharedMemorySize, SMEM_DYN);

    // bf16 splits of inputs/weights
    split_f32<<<(MROWS*DM/4 + 255)/256, 256>>>(x,       xhi, xlo, MROWS*DM/4);
    split_f32<<<(2*DI*DM/4  + 255)/256, 256>>>(W_in,    wih, wil, 2*DI*DM/4);
    split_f32<<<(XPC*DI/4   + 255)/256, 256>>>(W_xproj, wxh, wxl, XPC*DI/4);
    split_f32<<<(DI*DTR/4   + 255)/256, 256>>>(W_dt,    wdh, wdl, DI*DTR/4);
    split_f32<<<(DM*DI/4    + 255)/256, 256>>>(W_out,   woh, wol, DM*DI/4);

    // 1) in_proj: xz[4096,4096] = x @ W_in^T
    mma_gemm<<<dim3(32, 32), 256, SMEM_DYN>>>(xhi, xlo, DM, wih, wil, DM,
                                              xz, 2*DI, 2*DI, DM/64,
                                              nullptr, 0, nullptr, nullptr);
    // 2) conv + silu -> u (fp32 + bf16 split)
    conv_silu_kernel<<<(BB*LL*DI + 255)/256, 256>>>(xz, conv_w, conv_b, u, uhi, ulo);
    // 3) x_proj: xdbl[4096,96] = u @ W_xproj^T  (fp32 + bf16 split)
    mma_gemm<<<dim3(1, 32), 256, SMEM_DYN>>>(uhi, ulo, DI, wxh, wxl, DI,
                                             xdbl, XPC, XPC, DI/64,
                                             nullptr, 2, xdhi, xdlo);
    // 4) delta = softplus(dt_low @ W_dt^T + b_dt)
    mma_gemm<<<dim3(16, 32), 256, SMEM_DYN>>>(xdhi, xdlo, XPC, wdh, wdl, DTR,
                                              delta, DI, DI, DTR/64,
                                              b_dt, 1, nullptr, nullptr);
    // 5) selective scan + skip + gate -> yg (bf16 split)
    scan_kernel<<<512, 128>>>(delta, u, xdbl, xz, A_log, Dskip, yghi, yglo);
    // 6) out_proj: out[4096,1024] = yg @ W_out^T
    mma_gemm<<<dim3(8, 32), 256, SMEM_DYN>>>(yghi, yglo, DI, woh, wol, DI,
                                             out, DM, DM, DI/64,
                                             nullptr, 0, nullptr, nullptr);
}

// round 5
// speedup vs baseline: 1.9234x; 1.1279x over previous
#include <cuda_runtime.h>
#include <cuda_fp16.h>
#include <math.h>
#include <stdint.h>

#define BB   2
#define LL   2048
#define DM   1024
#define DI   2048
#define DS   16
#define DTR  64
#define MROWS (BB*LL)          /* 4096 */
#define XPC  (DTR + 2*DS)      /* 96   */
#define ZSPLIT 8               /* split-K factor for x_proj GEMM */

// ---------------- scratch (device globals; allocation-free) -----------------
__device__ float g_xz   [(size_t)MROWS * 2 * DI];   // 4096 x 4096 fp32 (xb | z)
__device__ float g_u    [(size_t)MROWS * DI];       // conv+silu fp32
__device__ float g_xdbl [(size_t)MROWS * XPC];      // fp32 dt_low | B | C
__device__ float g_delta[(size_t)MROWS * DI];       // softplus(dt) fp32
__device__ float g_xpart[(size_t)ZSPLIT * MROWS * XPC]; // split-K partials

__device__ __half g_xhi [(size_t)MROWS * DM];
__device__ __half g_xlo [(size_t)MROWS * DM];
__device__ __half g_uhi [(size_t)MROWS * DI];
__device__ __half g_ulo [(size_t)MROWS * DI];
__device__ __half g_xdhi[(size_t)MROWS * XPC];
__device__ __half g_xdlo[(size_t)MROWS * XPC];
__device__ __half g_yghi[(size_t)MROWS * DI];
__device__ __half g_yglo[(size_t)MROWS * DI];
__device__ __half g_wih [(size_t)(2*DI) * DM];      // W_in  (hi only, 2-seg)
__device__ __half g_wxh [(size_t)XPC * DI];
__device__ __half g_wxl [(size_t)XPC * DI];
__device__ __half g_wdh [(size_t)DI * DTR];
__device__ __half g_wdl [(size_t)DI * DTR];
__device__ __half g_woh [(size_t)DM * DI];          // W_out (hi only, 2-seg)

// ====================== helpers ==============================================
#define SW128(o) ((o) ^ (((o) >> 3) & 0x70))

__device__ __forceinline__ uint32_t smem_u32(const void* p) {
    uint32_t a;
    asm("{ .reg .u64 t; cvta.to.shared.u64 t, %1; cvt.u32.u64 %0, t; }"
        : "=r"(a) : "l"(p));
    return a;
}
__device__ __forceinline__ void cp16(uint32_t s, const void* g) {
    asm volatile("cp.async.cg.shared.global [%0], [%1], 16;"
                 :: "r"(s), "l"(g) : "memory");
}
#define CP_COMMIT()  asm volatile("cp.async.commit_group;" ::: "memory")
#define CP_WAIT(n)   asm volatile("cp.async.wait_group %0;" :: "n"(n) : "memory")

__device__ __forceinline__ void ldsm_x4(uint32_t* r, uint32_t addr) {
    asm volatile("ldmatrix.sync.aligned.m8n8.x4.shared.b16 {%0,%1,%2,%3}, [%4];"
        : "=r"(r[0]), "=r"(r[1]), "=r"(r[2]), "=r"(r[3]) : "r"(addr));
}
__device__ __forceinline__ void mma16816(float* d, const uint32_t* a, const uint32_t* b) {
    asm volatile("mma.sync.aligned.m16n8k16.row.col.f32.f16.f16.f32 "
        "{%0,%1,%2,%3}, {%4,%5,%6,%7}, {%8,%9}, {%0,%1,%2,%3};"
        : "+f"(d[0]), "+f"(d[1]), "+f"(d[2]), "+f"(d[3])
        : "r"(a[0]), "r"(a[1]), "r"(a[2]), "r"(a[3]), "r"(b[0]), "r"(b[1]));
}

// ====================== fp32 -> fp16 splits ==================================
__global__ __launch_bounds__(256)
void split2_f16(const float* __restrict__ s, __half* __restrict__ hi,
                __half* __restrict__ lo, int n4)
{
    int i = blockIdx.x * 256 + threadIdx.x;
    if (i >= n4) return;
    float4 v = ((const float4*)s)[i];
    __half h0 = __float2half(v.x), h1 = __float2half(v.y);
    __half h2 = __float2half(v.z), h3 = __float2half(v.w);
    __half2 H0; H0.x = h0; H0.y = h1;
    __half2 H1; H1.x = h2; H1.y = h3;
    ((__half2*)hi)[i*2+0] = H0;
    ((__half2*)hi)[i*2+1] = H1;
    __half2 L0, L1;
    L0.x = __float2half(v.x - __half2float(h0));
    L0.y = __float2half(v.y - __half2float(h1));
    L1.x = __float2half(v.z - __half2float(h2));
    L1.y = __float2half(v.w - __half2float(h3));
    ((__half2*)lo)[i*2+0] = L0;
    ((__half2*)lo)[i*2+1] = L1;
}

__global__ __launch_bounds__(256)
void cvt_f16(const float* __restrict__ s, __half* __restrict__ hi, int n4)
{
    int i = blockIdx.x * 256 + threadIdx.x;
    if (i >= n4) return;
    float4 v = ((const float4*)s)[i];
    __half2 H0; H0.x = __float2half(v.x); H0.y = __float2half(v.y);
    __half2 H1; H1.x = __float2half(v.z); H1.y = __float2half(v.w);
    ((__half2*)hi)[i*2+0] = H0;
    ((__half2*)hi)[i*2+1] = H1;
}

// ====================== split-fp16 HMMA GEMM =================================
// C[M,N] = A[M,K] * B[N,K]^T with A = Ah+Al (fp16 exact split).
// nseg=2: AhBh + AlBh           (B fp16-rounded; ~2.8e-4 RMS rel err)
// nseg=3: AhBh + AlBh + AhBl    (both corrected; ~1e-5)
// CTA 128x128, BK=64 fp16, 8 warps, 3-stage cp.async pipeline, SW128 swizzle.
// gridDim.z>1: deterministic split-K; partials to Cpart[z], no epilogue op.
// ep=0: fp32 C.  ep=1: C = softplus(acc + bias[col]).
#define NSTAGE 3
#define SMEM_DYN (NSTAGE*32*1024 + 1024)

__global__ __launch_bounds__(256, 2)
void mma_gemm(const __half* __restrict__ Ah, const __half* __restrict__ Al, int lda,
              const __half* __restrict__ Bh, const __half* __restrict__ Bl, int ldb,
              float* __restrict__ C, int ldc, int N, int K64, int nseg,
              const float* __restrict__ bias, int ep,
              float* __restrict__ Cpart)
{
    extern __shared__ char dsm[];

    const int tid = threadIdx.x;
    const int wid = tid >> 5;
    const int lid = tid & 31;
    const int brow = blockIdx.y * 128;
    const int bcol = blockIdx.x * 128;

    uint32_t sbase = (smem_u32(dsm) + 1023) & ~1023u;
    uint32_t sA[NSTAGE], sB[NSTAGE];
#pragma unroll
    for (int s = 0; s < NSTAGE; s++) {
        sA[s] = sbase + s * 32768;
        sB[s] = sbase + s * 32768 + 16384;
    }

    const int KT  = nseg * K64;
    const int per = KT / gridDim.z;
    const int t0  = blockIdx.z * per;
    const int t1  = t0 + per;

    const int mbase = (wid >> 1) * 32;
    const int nbase = (wid & 1) * 64;

    float acc[2][8][4];
#pragma unroll
    for (int i = 0; i < 2; i++)
#pragma unroll
        for (int j = 0; j < 8; j++)
#pragma unroll
            for (int k = 0; k < 4; k++) acc[i][j][k] = 0.f;

    auto load_tile = [&](int j) {
        int s  = j / K64;
        int kb = (j - s * K64) << 6;
        const __half* Ap = (s == 1) ? Al : Ah;
        const __half* Bp = (s == 2) ? Bl : Bh;
        int st = j % NSTAGE;
        uint32_t sa = sA[st];
        uint32_t sb = sB[st];
#pragma unroll
        for (int it = 0; it < 4; it++) {
            int slot = tid + it * 256;
            int rr = slot >> 3, ch = slot & 7;
            uint32_t off = SW128(rr * 128 + ch * 16);
            cp16(sa + off, Ap + (size_t)(brow + rr) * lda + kb + ch * 8);
        }
#pragma unroll
        for (int it = 0; it < 4; it++) {
            int slot = tid + it * 256;
            int rr = slot >> 3, ch = slot & 7;
            uint32_t off = SW128(rr * 128 + ch * 16);
            if (bcol + rr < N) {
                cp16(sb + off, Bp + (size_t)(bcol + rr) * ldb + kb + ch * 8);
            } else {
                asm volatile("st.shared.v4.b32 [%0], {%1, %1, %1, %1};"
                             :: "r"(sb + off), "r"(0) : "memory");
            }
        }
    };

    load_tile(t0); CP_COMMIT();
    if (t0 + 1 < t1) { load_tile(t0 + 1); CP_COMMIT(); }

    for (int kt = t0; kt < t1; kt++) {
        if (kt + 1 < t1) { CP_WAIT(1); }
        else             { CP_WAIT(0); }
        __syncthreads();
        if (kt + 2 < t1) { load_tile(kt + 2); CP_COMMIT(); }

        uint32_t sa = sA[kt % NSTAGE], sb = sB[kt % NSTAGE];
#pragma unroll
        for (int ks = 0; ks < 4; ks++) {
            uint32_t a[2][4], b[4][4];
#pragma unroll
            for (int mt = 0; mt < 2; mt++) {
                int row = mbase + mt * 16 + (lid & 15);
                int kb  = ks * 32 + ((lid >> 4) << 4);
                ldsm_x4(a[mt], sa + SW128(row * 128 + kb));
            }
#pragma unroll
            for (int bp = 0; bp < 4; bp++) {
                int nr = nbase + bp * 16 + (lid & 7) + ((lid >> 4) << 3);
                int kb = ks * 32 + (((lid >> 3) & 1) << 4);
                ldsm_x4(b[bp], sb + SW128(nr * 128 + kb));
            }
#pragma unroll
            for (int mt = 0; mt < 2; mt++)
#pragma unroll
                for (int nt = 0; nt < 8; nt++)
                    mma16816(acc[mt][nt], a[mt], &b[nt >> 1][(nt & 1) * 2]);
        }
    }

    // --- epilogue ---
    float* Cdst = C;
    int doep = ep;
    if (gridDim.z > 1) {
        Cdst = Cpart + (size_t)blockIdx.z * (size_t)(gridDim.y * 128) * ldc;
        doep = 0;
    }
#pragma unroll
    for (int mt = 0; mt < 2; mt++) {
#pragma unroll
        for (int nt = 0; nt < 8; nt++) {
            int c = bcol + nbase + nt * 8 + (lid & 3) * 2;
            if (c >= N) continue;
#pragma unroll
            for (int half = 0; half < 2; half++) {
                int r = brow + mbase + mt * 16 + (lid >> 2) + half * 8;
                float v0 = acc[mt][nt][half * 2 + 0];
                float v1 = acc[mt][nt][half * 2 + 1];
                if (doep == 1) {
                    v0 += bias[c];
                    v1 += bias[c + 1];
                    v0 = (v0 > 20.f) ? v0 : log1pf(__expf(v0));
                    v1 = (v1 > 20.f) ? v1 : log1pf(__expf(v1));
                }
                *(float2*)&Cdst[(size_t)r * ldc + c] = make_float2(v0, v1);
            }
        }
    }
}

// ---------------- split-K reduction for x_proj + fp16 re-split ---------------
__global__ __launch_bounds__(256)
void reduce_xproj(const float* __restrict__ part, float* __restrict__ xdbl,
                  __half* __restrict__ xdhi, __half* __restrict__ xdlo)
{
    int i = blockIdx.x * 256 + threadIdx.x;     // quad index
    const int n4 = MROWS * XPC / 4;
    if (i >= n4) return;
    float4 s = ((const float4*)part)[i];
#pragma unroll
    for (int z = 1; z < ZSPLIT; z++) {
        float4 p = ((const float4*)(part + (size_t)z * MROWS * XPC))[i];
        s.x += p.x; s.y += p.y; s.z += p.z; s.w += p.w;
    }
    ((float4*)xdbl)[i] = s;
    __half h0 = __float2half(s.x), h1 = __float2half(s.y);
    __half h2 = __float2half(s.z), h3 = __float2half(s.w);
    __half2 H0; H0.x = h0; H0.y = h1;
    __half2 H1; H1.x = h2; H1.y = h3;
    ((__half2*)xdhi)[i*2+0] = H0;
    ((__half2*)xdhi)[i*2+1] = H1;
    __half2 L0, L1;
    L0.x = __float2half(s.x - __half2float(h0));
    L0.y = __float2half(s.y - __half2float(h1));
    L1.x = __float2half(s.z - __half2float(h2));
    L1.y = __float2half(s.w - __half2float(h3));
    ((__half2*)xdlo)[i*2+0] = L0;
    ((__half2*)xdlo)[i*2+1] = L1;
}

// ---------------- causal depthwise conv (width 4) + bias + silu -------------
__global__ __launch_bounds__(256)
void conv_silu_kernel(const float* __restrict__ xz,
                      const float* __restrict__ cw,
                      const float* __restrict__ cb,
                      float* __restrict__ u,
                      __half* __restrict__ uhi,
                      __half* __restrict__ ulo)
{
    int idx = blockIdx.x * 256 + threadIdx.x;
    if (idx >= BB*LL*DI) return;
    int d = idx & (DI - 1);
    int t = (idx >> 11) & (LL - 1);
    size_t base = (size_t)(idx >> 11) * (2*DI) + d;

    float w0 = cw[d*4+0], w1 = cw[d*4+1], w2 = cw[d*4+2], w3 = cw[d*4+3];
    float acc = cb[d];
    if (t >= 3) acc = fmaf(xz[base - 3*(size_t)(2*DI)], w0, acc);
    if (t >= 2) acc = fmaf(xz[base - 2*(size_t)(2*DI)], w1, acc);
    if (t >= 1) acc = fmaf(xz[base -   (size_t)(2*DI)], w2, acc);
    acc = fmaf(xz[base], w3, acc);

    float sig = 1.f / (1.f + __expf(-acc));
    float v = acc * sig;
    u[idx] = v;
    __half h = __float2half(v);
    uhi[idx] = h;
    ulo[idx] = __float2half(v - __half2float(h));
}

// ---------------- selective scan + skip + gate -------------------------------
__global__ __launch_bounds__(128)
void scan_kernel(const float* __restrict__ delta,
                 const float* __restrict__ u,
                 const float* __restrict__ xdbl,
                 const float* __restrict__ xz,
                 const float* __restrict__ A_log,
                 const float* __restrict__ Dskip,
                 __half* __restrict__ yghi,
                 __half* __restrict__ yglo)
{
    int gtid = blockIdx.x * 128 + threadIdx.x;
    int ch = gtid >> 4;
    int nq = gtid & 15;
    int b  = ch >> 11;
    int d  = ch & (DI - 1);

    const float An = -__expf(A_log[d*DS + nq]);
    const float Dd = Dskip[d];
    float h = 0.f;

    const size_t rbase = (size_t)b * LL;

    float dtv = delta[rbase*DI + d];
    float uv  = u    [rbase*DI + d];
    float Bn  = xdbl [rbase*XPC + DTR + nq];
    float Cn  = xdbl [rbase*XPC + DTR + DS + nq];
    float zv  = xz   [rbase*(2*DI) + DI + d];

    for (int t = 0; t < LL; t++) {
        float dtv2 = 0.f, uv2 = 0.f, Bn2 = 0.f, Cn2 = 0.f, zv2 = 0.f;
        if (t + 1 < LL) {
            size_t nrow = rbase + t + 1;
            dtv2 = delta[nrow*DI + d];
            uv2  = u    [nrow*DI + d];
            Bn2  = xdbl [nrow*XPC + DTR + nq];
            Cn2  = xdbl [nrow*XPC + DTR + DS + nq];
            zv2  = xz   [nrow*(2*DI) + DI + d];
        }

        float dA = __expf(dtv * An);
        h = fmaf(dA, h, (dtv * uv) * Bn);
        float yp = h * Cn;
        yp += __shfl_xor_sync(0xffffffffu, yp, 1);
        yp += __shfl_xor_sync(0xffffffffu, yp, 2);
        yp += __shfl_xor_sync(0xffffffffu, yp, 4);
        yp += __shfl_xor_sync(0xffffffffu, yp, 8);

        if (nq == 0) {
            float yfull = yp + uv * Dd;
            float sig = 1.f / (1.f + __expf(-zv));
            float g = yfull * (zv * sig);
            size_t o = (rbase + t)*DI + d;
            __half hh = __float2half(g);
            yghi[o] = hh;
            yglo[o] = __float2half(g - __half2float(hh));
        }
        dtv = dtv2; uv = uv2; Bn = Bn2; Cn = Cn2; zv = zv2;
    }
}

// ---------------- launch -----------------------------------------------------
extern "C" void kernel_launch(void* const* d_in, const int* in_sizes, int n_in,
                              void* d_out, int out_size)
{
    (void)in_sizes; (void)n_in; (void)out_size;
    const float* x       = (const float*)d_in[0];
    const float* W_in    = (const float*)d_in[1];
    const float* conv_w  = (const float*)d_in[2];
    const float* conv_b  = (const float*)d_in[3];
    const float* W_xproj = (const float*)d_in[4];
    const float* W_dt    = (const float*)d_in[5];
    const float* b_dt    = (const float*)d_in[6];
    const float* A_log   = (const float*)d_in[7];
    const float* Dskip   = (const float*)d_in[8];
    const float* W_out   = (const float*)d_in[9];
    float* out = (float*)d_out;

    float *xz, *u, *xdbl, *delta, *xpart;
    __half *xhi, *xlo, *uhi, *ulo, *xdhi, *xdlo, *yghi, *yglo;
    __half *wih, *wxh, *wxl, *wdh, *wdl, *woh;
    cudaGetSymbolAddress((void**)&xz,    g_xz);
    cudaGetSymbolAddress((void**)&u,     g_u);
    cudaGetSymbolAddress((void**)&xdbl,  g_xdbl);
    cudaGetSymbolAddress((void**)&delta, g_delta);
    cudaGetSymbolAddress((void**)&xpart, g_xpart);
    cudaGetSymbolAddress((void**)&xhi,   g_xhi);
    cudaGetSymbolAddress((void**)&xlo,   g_xlo);
    cudaGetSymbolAddress((void**)&uhi,   g_uhi);
    cudaGetSymbolAddress((void**)&ulo,   g_ulo);
    cudaGetSymbolAddress((void**)&xdhi,  g_xdhi);
    cudaGetSymbolAddress((void**)&xdlo,  g_xdlo);
    cudaGetSymbolAddress((void**)&yghi,  g_yghi);
    cudaGetSymbolAddress((void**)&yglo,  g_yglo);
    cudaGetSymbolAddress((void**)&wih,   g_wih);
    cudaGetSymbolAddress((void**)&wxh,   g_wxh);
    cudaGetSymbolAddress((void**)&wxl,   g_wxl);
    cudaGetSymbolAddress((void**)&wdh,   g_wdh);
    cudaGetSymbolAddress((void**)&wdl,   g_wdl);
    cudaGetSymbolAddress((void**)&woh,   g_woh);

    cudaFuncSetAttribute(mma_gemm, cudaFuncAttributeMaxDynamicSharedMemorySize, SMEM_DYN);

    // fp16 conversions: A-side split2, B-side per-GEMM precision choice
    split2_f16<<<(MROWS*DM/4 + 255)/256, 256>>>(x,       xhi, xlo, MROWS*DM/4);
    cvt_f16   <<<(2*DI*DM/4  + 255)/256, 256>>>(W_in,    wih,      2*DI*DM/4);
    split2_f16<<<(XPC*DI/4   + 255)/256, 256>>>(W_xproj, wxh, wxl, XPC*DI/4);
    split2_f16<<<(DI*DTR/4   + 255)/256, 256>>>(W_dt,    wdh, wdl, DI*DTR/4);
    cvt_f16   <<<(DM*DI/4    + 255)/256, 256>>>(W_out,   woh,      DM*DI/4);

    // 1) in_proj: xz = x @ W_in^T   (2-seg: A exact, B fp16)
    mma_gemm<<<dim3(32, 32, 1), 256, SMEM_DYN>>>(
        xhi, xlo, DM, wih, nullptr, DM, xz, 2*DI, 2*DI, DM/64, 2,
        nullptr, 0, nullptr);
    // 2) conv + silu -> u (fp32 + fp16 split)
    conv_silu_kernel<<<(BB*LL*DI + 255)/256, 256>>>(xz, conv_w, conv_b, u, uhi, ulo);
    // 3) x_proj: xdbl = u @ W_xproj^T (3-seg, 8-way split-K) + reduce
    mma_gemm<<<dim3(1, 32, ZSPLIT), 256, SMEM_DYN>>>(
        uhi, ulo, DI, wxh, wxl, DI, nullptr, XPC, XPC, DI/64, 3,
        nullptr, 0, xpart);
    reduce_xproj<<<(MROWS*XPC/4 + 255)/256, 256>>>(xpart, xdbl, xdhi, xdlo);
    // 4) delta = softplus(dt_low @ W_dt^T + b_dt)   (3-seg)
    mma_gemm<<<dim3(16, 32, 1), 256, SMEM_DYN>>>(
        xdhi, xdlo, XPC, wdh, wdl, DTR, delta, DI, DI, DTR/64, 3,
        b_dt, 1, nullptr);
    // 5) selective scan + skip + gate -> yg (fp16 split)
    scan_kernel<<<512, 128>>>(delta, u, xdbl, xz, A_log, Dskip, yghi, yglo);
    // 6) out_proj: out = yg @ W_out^T   (2-seg)
    mma_gemm<<<dim3(8, 32, 1), 256, SMEM_DYN>>>(
        yghi, yglo, DI, woh, nullptr, DI, out, DM, DM, DI/64, 2,
        nullptr, 0, nullptr);
}

// round 6
// speedup vs baseline: 3.1488x; 1.6371x over previous
#include <cuda_runtime.h>
#include <cuda_fp16.h>
#include <math.h>
#include <stdint.h>

#define BB   2
#define LL   2048
#define DM   1024
#define DI   2048
#define DS   16
#define DTR  64
#define MROWS (BB*LL)          /* 4096 */
#define XPC  (DTR + 2*DS)      /* 96   */
#define ZSPLIT 8               /* split-K factor for x_proj GEMM */
#define NCHUNK 8               /* time chunks for parallel scan */
#define TC (LL/NCHUNK)         /* 256 steps per chunk */

// ---------------- scratch (device globals; allocation-free) -----------------
__device__ float g_xz   [(size_t)MROWS * 2 * DI];
__device__ float g_u    [(size_t)MROWS * DI];
__device__ float g_xdbl [(size_t)MROWS * XPC];
__device__ float g_delta[(size_t)MROWS * DI];
__device__ float g_xpart[(size_t)ZSPLIT * MROWS * XPC];
__device__ float g_P [(size_t)NCHUNK * MROWS * DS];   // chunk propagators
__device__ float g_S [(size_t)NCHUNK * MROWS * DS];   // chunk local sums
__device__ float g_H0[(size_t)NCHUNK * MROWS * DS];   // chunk start states

__device__ __half g_xhi [(size_t)MROWS * DM];
__device__ __half g_xlo [(size_t)MROWS * DM];
__device__ __half g_uhi [(size_t)MROWS * DI];
__device__ __half g_ulo [(size_t)MROWS * DI];
__device__ __half g_xdhi[(size_t)MROWS * XPC];
__device__ __half g_xdlo[(size_t)MROWS * XPC];
__device__ __half g_yghi[(size_t)MROWS * DI];
__device__ __half g_yglo[(size_t)MROWS * DI];
__device__ __half g_wih [(size_t)(2*DI) * DM];
__device__ __half g_wxh [(size_t)XPC * DI];
__device__ __half g_wxl [(size_t)XPC * DI];
__device__ __half g_wdh [(size_t)DI * DTR];
__device__ __half g_wdl [(size_t)DI * DTR];
__device__ __half g_woh [(size_t)DM * DI];

// ====================== helpers ==============================================
#define SW128(o) ((o) ^ (((o) >> 3) & 0x70))

__device__ __forceinline__ uint32_t smem_u32(const void* p) {
    uint32_t a;
    asm("{ .reg .u64 t; cvta.to.shared.u64 t, %1; cvt.u32.u64 %0, t; }"
        : "=r"(a) : "l"(p));
    return a;
}
__device__ __forceinline__ void cp16(uint32_t s, const void* g) {
    asm volatile("cp.async.cg.shared.global [%0], [%1], 16;"
                 :: "r"(s), "l"(g) : "memory");
}
#define CP_COMMIT()  asm volatile("cp.async.commit_group;" ::: "memory")
#define CP_WAIT(n)   asm volatile("cp.async.wait_group %0;" :: "n"(n) : "memory")

__device__ __forceinline__ void ldsm_x4(uint32_t* r, uint32_t addr) {
    asm volatile("ldmatrix.sync.aligned.m8n8.x4.shared.b16 {%0,%1,%2,%3}, [%4];"
        : "=r"(r[0]), "=r"(r[1]), "=r"(r[2]), "=r"(r[3]) : "r"(addr));
}
__device__ __forceinline__ void mma16816(float* d, const uint32_t* a, const uint32_t* b) {
    asm volatile("mma.sync.aligned.m16n8k16.row.col.f32.f16.f16.f32 "
        "{%0,%1,%2,%3}, {%4,%5,%6,%7}, {%8,%9}, {%0,%1,%2,%3};"
        : "+f"(d[0]), "+f"(d[1]), "+f"(d[2]), "+f"(d[3])
        : "r"(a[0]), "r"(a[1]), "r"(a[2]), "r"(a[3]), "r"(b[0]), "r"(b[1]));
}

// ====================== fp32 -> fp16 splits ==================================
__global__ __launch_bounds__(256)
void split2_f16(const float* __restrict__ s, __half* __restrict__ hi,
                __half* __restrict__ lo, int n4)
{
    int i = blockIdx.x * 256 + threadIdx.x;
    if (i >= n4) return;
    float4 v = ((const float4*)s)[i];
    __half h0 = __float2half(v.x), h1 = __float2half(v.y);
    __half h2 = __float2half(v.z), h3 = __float2half(v.w);
    __half2 H0; H0.x = h0; H0.y = h1;
    __half2 H1; H1.x = h2; H1.y = h3;
    ((__half2*)hi)[i*2+0] = H0;
    ((__half2*)hi)[i*2+1] = H1;
    __half2 L0, L1;
    L0.x = __float2half(v.x - __half2float(h0));
    L0.y = __float2half(v.y - __half2float(h1));
    L1.x = __float2half(v.z - __half2float(h2));
    L1.y = __float2half(v.w - __half2float(h3));
    ((__half2*)lo)[i*2+0] = L0;
    ((__half2*)lo)[i*2+1] = L1;
}

__global__ __launch_bounds__(256)
void cvt_f16(const float* __restrict__ s, __half* __restrict__ hi, int n4)
{
    int i = blockIdx.x * 256 + threadIdx.x;
    if (i >= n4) return;
    float4 v = ((const float4*)s)[i];
    __half2 H0; H0.x = __float2half(v.x); H0.y = __float2half(v.y);
    __half2 H1; H1.x = __float2half(v.z); H1.y = __float2half(v.w);
    ((__half2*)hi)[i*2+0] = H0;
    ((__half2*)hi)[i*2+1] = H1;
}

// ====================== split-fp16 HMMA GEMM =================================
#define NSTAGE 3
#define SMEM_DYN (NSTAGE*32*1024 + 1024)

__global__ __launch_bounds__(256, 2)
void mma_gemm(const __half* __restrict__ Ah, const __half* __restrict__ Al, int lda,
              const __half* __restrict__ Bh, const __half* __restrict__ Bl, int ldb,
              float* __restrict__ C, int ldc, int N, int K64, int nseg,
              const float* __restrict__ bias, int ep,
              float* __restrict__ Cpart)
{
    extern __shared__ char dsm[];

    const int tid = threadIdx.x;
    const int wid = tid >> 5;
    const int lid = tid & 31;
    const int brow = blockIdx.y * 128;
    const int bcol = blockIdx.x * 128;

    uint32_t sbase = (smem_u32(dsm) + 1023) & ~1023u;
    uint32_t sA[NSTAGE], sB[NSTAGE];
#pragma unroll
    for (int s = 0; s < NSTAGE; s++) {
        sA[s] = sbase + s * 32768;
        sB[s] = sbase + s * 32768 + 16384;
    }

    const int KT  = nseg * K64;
    const int per = KT / gridDim.z;
    const int t0  = blockIdx.z * per;
    const int t1  = t0 + per;

    const int mbase = (wid >> 1) * 32;
    const int nbase = (wid & 1) * 64;

    float acc[2][8][4];
#pragma unroll
    for (int i = 0; i < 2; i++)
#pragma unroll
        for (int j = 0; j < 8; j++)
#pragma unroll
            for (int k = 0; k < 4; k++) acc[i][j][k] = 0.f;

    auto load_tile = [&](int j) {
        int s  = j / K64;
        int kb = (j - s * K64) << 6;
        const __half* Ap = (s == 1) ? Al : Ah;
        const __half* Bp = (s == 2) ? Bl : Bh;
        int st = j % NSTAGE;
        uint32_t sa = sA[st];
        uint32_t sb = sB[st];
#pragma unroll
        for (int it = 0; it < 4; it++) {
            int slot = tid + it * 256;
            int rr = slot >> 3, ch = slot & 7;
            uint32_t off = SW128(rr * 128 + ch * 16);
            cp16(sa + off, Ap + (size_t)(brow + rr) * lda + kb + ch * 8);
        }
#pragma unroll
        for (int it = 0; it < 4; it++) {
            int slot = tid + it * 256;
            int rr = slot >> 3, ch = slot & 7;
            uint32_t off = SW128(rr * 128 + ch * 16);
            if (bcol + rr < N) {
                cp16(sb + off, Bp + (size_t)(bcol + rr) * ldb + kb + ch * 8);
            } else {
                asm volatile("st.shared.v4.b32 [%0], {%1, %1, %1, %1};"
                             :: "r"(sb + off), "r"(0) : "memory");
            }
        }
    };

    load_tile(t0); CP_COMMIT();
    if (t0 + 1 < t1) { load_tile(t0 + 1); CP_COMMIT(); }

    for (int kt = t0; kt < t1; kt++) {
        if (kt + 1 < t1) { CP_WAIT(1); }
        else             { CP_WAIT(0); }
        __syncthreads();
        if (kt + 2 < t1) { load_tile(kt + 2); CP_COMMIT(); }

        uint32_t sa = sA[kt % NSTAGE], sb = sB[kt % NSTAGE];
#pragma unroll
        for (int ks = 0; ks < 4; ks++) {
            uint32_t a[2][4], b[4][4];
#pragma unroll
            for (int mt = 0; mt < 2; mt++) {
                int row = mbase + mt * 16 + (lid & 15);
                int kb  = ks * 32 + ((lid >> 4) << 4);
                ldsm_x4(a[mt], sa + SW128(row * 128 + kb));
            }
#pragma unroll
            for (int bp = 0; bp < 4; bp++) {
                int nr = nbase + bp * 16 + (lid & 7) + ((lid >> 4) << 3);
                int kb = ks * 32 + (((lid >> 3) & 1) << 4);
                ldsm_x4(b[bp], sb + SW128(nr * 128 + kb));
            }
#pragma unroll
            for (int mt = 0; mt < 2; mt++)
#pragma unroll
                for (int nt = 0; nt < 8; nt++)
                    mma16816(acc[mt][nt], a[mt], &b[nt >> 1][(nt & 1) * 2]);
        }
    }

    float* Cdst = C;
    int doep = ep;
    if (gridDim.z > 1) {
        Cdst = Cpart + (size_t)blockIdx.z * (size_t)(gridDim.y * 128) * ldc;
        doep = 0;
    }
#pragma unroll
    for (int mt = 0; mt < 2; mt++) {
#pragma unroll
        for (int nt = 0; nt < 8; nt++) {
            int c = bcol + nbase + nt * 8 + (lid & 3) * 2;
            if (c >= N) continue;
#pragma unroll
            for (int half = 0; half < 2; half++) {
                int r = brow + mbase + mt * 16 + (lid >> 2) + half * 8;
                float v0 = acc[mt][nt][half * 2 + 0];
                float v1 = acc[mt][nt][half * 2 + 1];
                if (doep == 1) {
                    v0 += bias[c];
                    v1 += bias[c + 1];
                    v0 = (v0 > 20.f) ? v0 : log1pf(__expf(v0));
                    v1 = (v1 > 20.f) ? v1 : log1pf(__expf(v1));
                }
                *(float2*)&Cdst[(size_t)r * ldc + c] = make_float2(v0, v1);
            }
        }
    }
}

// ---------------- split-K reduction for x_proj + fp16 re-split ---------------
__global__ __launch_bounds__(256)
void reduce_xproj(const float* __restrict__ part, float* __restrict__ xdbl,
                  __half* __restrict__ xdhi, __half* __restrict__ xdlo)
{
    int i = blockIdx.x * 256 + threadIdx.x;
    const int n4 = MROWS * XPC / 4;
    if (i >= n4) return;
    float4 s = ((const float4*)part)[i];
#pragma unroll
    for (int z = 1; z < ZSPLIT; z++) {
        float4 p = ((const float4*)(part + (size_t)z * MROWS * XPC))[i];
        s.x += p.x; s.y += p.y; s.z += p.z; s.w += p.w;
    }
    ((float4*)xdbl)[i] = s;
    __half h0 = __float2half(s.x), h1 = __float2half(s.y);
    __half h2 = __float2half(s.z), h3 = __float2half(s.w);
    __half2 H0; H0.x = h0; H0.y = h1;
    __half2 H1; H1.x = h2; H1.y = h3;
    ((__half2*)xdhi)[i*2+0] = H0;
    ((__half2*)xdhi)[i*2+1] = H1;
    __half2 L0, L1;
    L0.x = __float2half(s.x - __half2float(h0));
    L0.y = __float2half(s.y - __half2float(h1));
    L1.x = __float2half(s.z - __half2float(h2));
    L1.y = __float2half(s.w - __half2float(h3));
    ((__half2*)xdlo)[i*2+0] = L0;
    ((__half2*)xdlo)[i*2+1] = L1;
}

// ---------------- causal depthwise conv (width 4) + bias + silu -------------
__global__ __launch_bounds__(256)
void conv_silu_kernel(const float* __restrict__ xz,
                      const float* __restrict__ cw,
                      const float* __restrict__ cb,
                      float* __restrict__ u,
                      __half* __restrict__ uhi,
                      __half* __restrict__ ulo)
{
    int idx = blockIdx.x * 256 + threadIdx.x;
    if (idx >= BB*LL*DI) return;
    int d = idx & (DI - 1);
    int t = (idx >> 11) & (LL - 1);
    size_t base = (size_t)(idx >> 11) * (2*DI) + d;

    float w0 = cw[d*4+0], w1 = cw[d*4+1], w2 = cw[d*4+2], w3 = cw[d*4+3];
    float acc = cb[d];
    if (t >= 3) acc = fmaf(xz[base - 3*(size_t)(2*DI)], w0, acc);
    if (t >= 2) acc = fmaf(xz[base - 2*(size_t)(2*DI)], w1, acc);
    if (t >= 1) acc = fmaf(xz[base -   (size_t)(2*DI)], w2, acc);
    acc = fmaf(xz[base], w3, acc);

    float sig = 1.f / (1.f + __expf(-acc));
    float v = acc * sig;
    u[idx] = v;
    __half h = __float2half(v);
    uhi[idx] = h;
    ulo[idx] = __float2half(v - __half2float(h));
}

// ---------------- parallel scan, pass 1: chunk-local (P, S) ------------------
// h_{t+1} = dA_t h_t + b_t over a TC-chunk starting from 0.
// P = prod dA = exp(An * sum dt)  (exp-of-sum: ONE exp per chunk)
__global__ __launch_bounds__(128)
void scan_pass1(const float* __restrict__ delta,
                const float* __restrict__ u,
                const float* __restrict__ xdbl,
                const float* __restrict__ A_log,
                float* __restrict__ P, float* __restrict__ S)
{
    int gtid = blockIdx.x * 128 + threadIdx.x;
    int ch = gtid >> 4;
    int nq = gtid & 15;
    int b  = ch >> 11;
    int d  = ch & (DI - 1);
    int c  = blockIdx.y;

    const float An = -__expf(A_log[d*DS + nq]);
    float h = 0.f, sdt = 0.f;
    const size_t rbase = (size_t)b * LL + c * TC;

    float dtv = delta[rbase*DI + d];
    float uv  = u    [rbase*DI + d];
    float Bn  = xdbl [rbase*XPC + DTR + nq];

    for (int t = 0; t < TC; t++) {
        float dtv2 = 0.f, uv2 = 0.f, Bn2 = 0.f;
        if (t + 1 < TC) {
            size_t nrow = rbase + t + 1;
            dtv2 = delta[nrow*DI + d];
            uv2  = u    [nrow*DI + d];
            Bn2  = xdbl [nrow*XPC + DTR + nq];
        }
        sdt += dtv;
        float dA = __expf(dtv * An);
        h = fmaf(dA, h, (dtv * uv) * Bn);
        dtv = dtv2; uv = uv2; Bn = Bn2;
    }
    size_t o = ((size_t)c * MROWS + ch) * DS + nq;
    P[o] = __expf(An * sdt);
    S[o] = h;
}

// ---------------- parallel scan, combine: chunk start states -----------------
__global__ __launch_bounds__(256)
void scan_combine(const float* __restrict__ P, const float* __restrict__ S,
                  float* __restrict__ H0)
{
    int i = blockIdx.x * 256 + threadIdx.x;     // (ch*DS + nq)
    if (i >= MROWS * DS) return;
    float h = 0.f;
    H0[i] = 0.f;
#pragma unroll
    for (int c = 0; c < NCHUNK - 1; c++) {
        size_t o = (size_t)c * MROWS * DS + i;
        h = fmaf(P[o], h, S[o]);
        H0[(size_t)(c+1) * MROWS * DS + i] = h;
    }
}

// ---------------- parallel scan, pass 2: outputs + skip + gate ---------------
__global__ __launch_bounds__(128)
void scan_pass2(const float* __restrict__ delta,
                const float* __restrict__ u,
                const float* __restrict__ xdbl,
                const float* __restrict__ xz,
                const float* __restrict__ A_log,
                const float* __restrict__ Dskip,
                const float* __restrict__ H0,
                __half* __restrict__ yghi,
                __half* __restrict__ yglo)
{
    int gtid = blockIdx.x * 128 + threadIdx.x;
    int ch = gtid >> 4;
    int nq = gtid & 15;
    int b  = ch >> 11;
    int d  = ch & (DI - 1);
    int c  = blockIdx.y;

    const float An = -__expf(A_log[d*DS + nq]);
    const float Dd = Dskip[d];
    float h = H0[((size_t)c * MROWS + ch) * DS + nq];
    const size_t rbase = (size_t)b * LL + c * TC;

    float dtv = delta[rbase*DI + d];
    float uv  = u    [rbase*DI + d];
    float Bn  = xdbl [rbase*XPC + DTR + nq];
    float Cn  = xdbl [rbase*XPC + DTR + DS + nq];
    float zv  = xz   [rbase*(2*DI) + DI + d];

    for (int t = 0; t < TC; t++) {
        float dtv2 = 0.f, uv2 = 0.f, Bn2 = 0.f, Cn2 = 0.f, zv2 = 0.f;
        if (t + 1 < TC) {
            size_t nrow = rbase + t + 1;
            dtv2 = delta[nrow*DI + d];
            uv2  = u    [nrow*DI + d];
            Bn2  = xdbl [nrow*XPC + DTR + nq];
            Cn2  = xdbl [nrow*XPC + DTR + DS + nq];
            zv2  = xz   [nrow*(2*DI) + DI + d];
        }

        float dA = __expf(dtv * An);
        h = fmaf(dA, h, (dtv * uv) * Bn);
        float yp = h * Cn;
        yp += __shfl_xor_sync(0xffffffffu, yp, 1);
        yp += __shfl_xor_sync(0xffffffffu, yp, 2);
        yp += __shfl_xor_sync(0xffffffffu, yp, 4);
        yp += __shfl_xor_sync(0xffffffffu, yp, 8);

        if (nq == 0) {
            float yfull = yp + uv * Dd;
            float sig = 1.f / (1.f + __expf(-zv));
            float g = yfull * (zv * sig);
            size_t o = (rbase + t)*DI + d;
            __half hh = __float2half(g);
            yghi[o] = hh;
            yglo[o] = __float2half(g - __half2float(hh));
        }
        dtv = dtv2; uv = uv2; Bn = Bn2; Cn = Cn2; zv = zv2;
    }
}

// ---------------- launch -----------------------------------------------------
extern "C" void kernel_launch(void* const* d_in, const int* in_sizes, int n_in,
                              void* d_out, int out_size)
{
    (void)in_sizes; (void)n_in; (void)out_size;
    const float* x       = (const float*)d_in[0];
    const float* W_in    = (const float*)d_in[1];
    const float* conv_w  = (const float*)d_in[2];
    const float* conv_b  = (const float*)d_in[3];
    const float* W_xproj = (const float*)d_in[4];
    const float* W_dt    = (const float*)d_in[5];
    const float* b_dt    = (const float*)d_in[6];
    const float* A_log   = (const float*)d_in[7];
    const float* Dskip   = (const float*)d_in[8];
    const float* W_out   = (const float*)d_in[9];
    float* out = (float*)d_out;

    float *xz, *u, *xdbl, *delta, *xpart, *Pb, *Sb, *H0b;
    __half *xhi, *xlo, *uhi, *ulo, *xdhi, *xdlo, *yghi, *yglo;
    __half *wih, *wxh, *wxl, *wdh, *wdl, *woh;
    cudaGetSymbolAddress((void**)&xz,    g_xz);
    cudaGetSymbolAddress((void**)&u,     g_u);
    cudaGetSymbolAddress((void**)&xdbl,  g_xdbl);
    cudaGetSymbolAddress((void**)&delta, g_delta);
    cudaGetSymbolAddress((void**)&xpart, g_xpart);
    cudaGetSymbolAddress((void**)&Pb,    g_P);
    cudaGetSymbolAddress((void**)&Sb,    g_S);
    cudaGetSymbolAddress((void**)&H0b,   g_H0);
    cudaGetSymbolAddress((void**)&xhi,   g_xhi);
    cudaGetSymbolAddress((void**)&xlo,   g_xlo);
    cudaGetSymbolAddress((void**)&uhi,   g_uhi);
    cudaGetSymbolAddress((void**)&ulo,   g_ulo);
    cudaGetSymbolAddress((void**)&xdhi,  g_xdhi);
    cudaGetSymbolAddress((void**)&xdlo,  g_xdlo);
    cudaGetSymbolAddress((void**)&yghi,  g_yghi);
    cudaGetSymbolAddress((void**)&yglo,  g_yglo);
    cudaGetSymbolAddress((void**)&wih,   g_wih);
    cudaGetSymbolAddress((void**)&wxh,   g_wxh);
    cudaGetSymbolAddress((void**)&wxl,   g_wxl);
    cudaGetSymbolAddress((void**)&wdh,   g_wdh);
    cudaGetSymbolAddress((void**)&wdl,   g_wdl);
    cudaGetSymbolAddress((void**)&woh,   g_woh);

    cudaFuncSetAttribute(mma_gemm, cudaFuncAttributeMaxDynamicSharedMemorySize, SMEM_DYN);

    // launches 0-2: gemm1's inputs (gemm1 lands at profiled index 3)
    split2_f16<<<(MROWS*DM/4 + 255)/256, 256>>>(x,       xhi, xlo, MROWS*DM/4);
    cvt_f16   <<<(2*DI*DM/4  + 255)/256, 256>>>(W_in,    wih,      2*DI*DM/4);
    split2_f16<<<(XPC*DI/4   + 255)/256, 256>>>(W_xproj, wxh, wxl, XPC*DI/4);

    // 1) in_proj: xz = x @ W_in^T   (2-seg)   [launch index 3 -> ncu target]
    mma_gemm<<<dim3(32, 32, 1), 256, SMEM_DYN>>>(
        xhi, xlo, DM, wih, nullptr, DM, xz, 2*DI, 2*DI, DM/64, 2,
        nullptr, 0, nullptr);

    split2_f16<<<(DI*DTR/4   + 255)/256, 256>>>(W_dt,    wdh, wdl, DI*DTR/4);
    cvt_f16   <<<(DM*DI/4    + 255)/256, 256>>>(W_out,   woh,      DM*DI/4);

    // 2) conv + silu -> u (fp32 + fp16 split)
    conv_silu_kernel<<<(BB*LL*DI + 255)/256, 256>>>(xz, conv_w, conv_b, u, uhi, ulo);
    // 3) x_proj: xdbl = u @ W_xproj^T (3-seg, 8-way split-K) + reduce
    mma_gemm<<<dim3(1, 32, ZSPLIT), 256, SMEM_DYN>>>(
        uhi, ulo, DI, wxh, wxl, DI, nullptr, XPC, XPC, DI/64, 3,
        nullptr, 0, xpart);
    reduce_xproj<<<(MROWS*XPC/4 + 255)/256, 256>>>(xpart, xdbl, xdhi, xdlo);
    // 4) delta = softplus(dt_low @ W_dt^T + b_dt)   (3-seg)
    mma_gemm<<<dim3(16, 32, 1), 256, SMEM_DYN>>>(
        xdhi, xdlo, XPC, wdh, wdl, DTR, delta, DI, DI, DTR/64, 3,
        b_dt, 1, nullptr);
    // 5) parallel selective scan (8 chunks): pass1 -> combine -> pass2
    scan_pass1<<<dim3(512, NCHUNK), 128>>>(delta, u, xdbl, A_log, Pb, Sb);
    scan_combine<<<(MROWS*DS + 255)/256, 256>>>(Pb, Sb, H0b);
    scan_pass2<<<dim3(512, NCHUNK), 128>>>(delta, u, xdbl, xz, A_log, Dskip,
                                           H0b, yghi, yglo);
    // 6) out_proj: out = yg @ W_out^T   (2-seg)
    mma_gemm<<<dim3(8, 32, 1), 256, SMEM_DYN>>>(
        yghi, yglo, DI, woh, nullptr, DI, out, DM, DM, DI/64, 2,
        nullptr, 0, nullptr);
}

// round 7
// speedup vs baseline: 3.5133x; 1.1158x over previous
#include <cuda_runtime.h>
#include <cuda_fp16.h>
#include <math.h>
#include <stdint.h>

#define BB   2
#define LL   2048
#define DM   1024
#define DI   2048
#define DS   16
#define DTR  64
#define MROWS (BB*LL)          /* 4096 */
#define XPC  (DTR + 2*DS)      /* 96   */
#define ZSPLIT 8               /* split-K factor for x_proj GEMM */
#define NCHUNK 16              /* time chunks for parallel scan */
#define TC (LL/NCHUNK)         /* 128 steps per chunk */

// ---------------- scratch (device globals; allocation-free) -----------------
__device__ float g_xz   [(size_t)MROWS * 2 * DI];
__device__ float g_u    [(size_t)MROWS * DI];
__device__ float g_xdbl [(size_t)MROWS * XPC];
__device__ float g_delta[(size_t)MROWS * DI];
__device__ float g_xpart[(size_t)ZSPLIT * MROWS * XPC];
__device__ float g_P [(size_t)NCHUNK * MROWS * DS];
__device__ float g_S [(size_t)NCHUNK * MROWS * DS];
__device__ float g_H0[(size_t)NCHUNK * MROWS * DS];

__device__ __half g_xhi [(size_t)MROWS * DM];
__device__ __half g_xlo [(size_t)MROWS * DM];
__device__ __half g_uhi [(size_t)MROWS * DI];
__device__ __half g_ulo [(size_t)MROWS * DI];
__device__ __half g_xdhi[(size_t)MROWS * XPC];
__device__ __half g_xdlo[(size_t)MROWS * XPC];
__device__ __half g_yghi[(size_t)MROWS * DI];
__device__ __half g_yglo[(size_t)MROWS * DI];
__device__ __half g_wih [(size_t)(2*DI) * DM];
__device__ __half g_wxh [(size_t)XPC * DI];
__device__ __half g_wxl [(size_t)XPC * DI];
__device__ __half g_wdh [(size_t)DI * DTR];
__device__ __half g_wdl [(size_t)DI * DTR];
__device__ __half g_woh [(size_t)DM * DI];

// ====================== helpers ==============================================
#define SW128(o) ((o) ^ (((o) >> 3) & 0x70))

__device__ __forceinline__ uint32_t smem_u32(const void* p) {
    uint32_t a;
    asm("{ .reg .u64 t; cvta.to.shared.u64 t, %1; cvt.u32.u64 %0, t; }"
        : "=r"(a) : "l"(p));
    return a;
}
__device__ __forceinline__ void cp16(uint32_t s, const void* g) {
    asm volatile("cp.async.cg.shared.global [%0], [%1], 16;"
                 :: "r"(s), "l"(g) : "memory");
}
#define CP_COMMIT()  asm volatile("cp.async.commit_group;" ::: "memory")
#define CP_WAIT(n)   asm volatile("cp.async.wait_group %0;" :: "n"(n) : "memory")

__device__ __forceinline__ void ldsm_x4(uint32_t* r, uint32_t addr) {
    asm volatile("ldmatrix.sync.aligned.m8n8.x4.shared.b16 {%0,%1,%2,%3}, [%4];"
        : "=r"(r[0]), "=r"(r[1]), "=r"(r[2]), "=r"(r[3]) : "r"(addr));
}
__device__ __forceinline__ void mma16816(float* d, const uint32_t* a, const uint32_t* b) {
    asm volatile("mma.sync.aligned.m16n8k16.row.col.f32.f16.f16.f32 "
        "{%0,%1,%2,%3}, {%4,%5,%6,%7}, {%8,%9}, {%0,%1,%2,%3};"
        : "+f"(d[0]), "+f"(d[1]), "+f"(d[2]), "+f"(d[3])
        : "r"(a[0]), "r"(a[1]), "r"(a[2]), "r"(a[3]), "r"(b[0]), "r"(b[1]));
}

// ====================== fp32 -> fp16 splits ==================================
__global__ __launch_bounds__(256)
void split2_f16(const float* __restrict__ s, __half* __restrict__ hi,
                __half* __restrict__ lo, int n4)
{
    int i = blockIdx.x * 256 + threadIdx.x;
    if (i >= n4) return;
    float4 v = ((const float4*)s)[i];
    __half h0 = __float2half(v.x), h1 = __float2half(v.y);
    __half h2 = __float2half(v.z), h3 = __float2half(v.w);
    __half2 H0; H0.x = h0; H0.y = h1;
    __half2 H1; H1.x = h2; H1.y = h3;
    ((__half2*)hi)[i*2+0] = H0;
    ((__half2*)hi)[i*2+1] = H1;
    __half2 L0, L1;
    L0.x = __float2half(v.x - __half2float(h0));
    L0.y = __float2half(v.y - __half2float(h1));
    L1.x = __float2half(v.z - __half2float(h2));
    L1.y = __float2half(v.w - __half2float(h3));
    ((__half2*)lo)[i*2+0] = L0;
    ((__half2*)lo)[i*2+1] = L1;
}

__global__ __launch_bounds__(256)
void cvt_f16(const float* __restrict__ s, __half* __restrict__ hi, int n4)
{
    int i = blockIdx.x * 256 + threadIdx.x;
    if (i >= n4) return;
    float4 v = ((const float4*)s)[i];
    __half2 H0; H0.x = __float2half(v.x); H0.y = __float2half(v.y);
    __half2 H1; H1.x = __float2half(v.z); H1.y = __float2half(v.w);
    ((__half2*)hi)[i*2+0] = H0;
    ((__half2*)hi)[i*2+1] = H1;
}

// ====================== split-fp16 HMMA GEMM =================================
// C[M,N] = A[M,K]*B[N,K]^T, A = Ah+Al exact fp16 split.
// nseg=2: AhBh+AlBh.  nseg=3: +AhBl.
// zcut: columns >= zcut use segment 0 only (gate-half precision cut).
#define NSTAGE 3
#define SMEM_DYN (NSTAGE*32*1024 + 1024)

__global__ __launch_bounds__(256, 2)
void mma_gemm(const __half* __restrict__ Ah, const __half* __restrict__ Al, int lda,
              const __half* __restrict__ Bh, const __half* __restrict__ Bl, int ldb,
              float* __restrict__ C, int ldc, int N, int K64, int nseg, int zcut,
              const float* __restrict__ bias, int ep,
              float* __restrict__ Cpart)
{
    extern __shared__ char dsm[];

    const int tid = threadIdx.x;
    const int wid = tid >> 5;
    const int lid = tid & 31;
    const int brow = blockIdx.y * 128;
    const int bcol = blockIdx.x * 128;

    uint32_t sbase = (smem_u32(dsm) + 1023) & ~1023u;
    uint32_t sA[NSTAGE], sB[NSTAGE];
#pragma unroll
    for (int s = 0; s < NSTAGE; s++) {
        sA[s] = sbase + s * 32768;
        sB[s] = sbase + s * 32768 + 16384;
    }

    int KT = nseg * K64;
    if (bcol >= zcut) KT = K64;          // gate half: segment 0 only
    const int per = KT / gridDim.z;
    const int t0  = blockIdx.z * per;
    const int t1  = t0 + per;

    // ---- hoisted loader addressing (loop-invariant) ----
    const int lrr = tid >> 3;            // base row 0..31
    const int lch = tid & 7;             // 16B chunk 0..7
    uint32_t loff[4];                    // swizzled smem offsets (A and B share)
    uint32_t rowA[4], rowB[4];           // element offsets into A/B
    bool     bok[4];
#pragma unroll
    for (int it = 0; it < 4; it++) {
        int rr = lrr + it * 32;
        loff[it] = SW128(rr * 128 + lch * 16);
        rowA[it] = (uint32_t)(brow + rr) * (uint32_t)lda + lch * 8;
        rowB[it] = (uint32_t)(bcol + rr) * (uint32_t)ldb + lch * 8;
        bok[it]  = (bcol + rr) < N;
    }

    const int mbase = (wid >> 1) * 32;
    const int nbase = (wid & 1) * 64;

    // ---- hoisted ldmatrix offsets: addr(ks) = off ^ (ks<<5) ----
    uint32_t aoff[2], boff[4];
#pragma unroll
    for (int mt = 0; mt < 2; mt++) {
        int row = mbase + mt * 16 + (lid & 15);
        aoff[mt] = SW128(row * 128 + ((lid >> 4) << 4));
    }
#pragma unroll
    for (int bp = 0; bp < 4; bp++) {
        int nr = nbase + bp * 16 + (lid & 7) + ((lid >> 4) << 3);
        boff[bp] = SW128(nr * 128 + (((lid >> 3) & 1) << 4));
    }

    float acc[2][8][4];
#pragma unroll
    for (int i = 0; i < 2; i++)
#pragma unroll
        for (int j = 0; j < 8; j++)
#pragma unroll
            for (int k = 0; k < 4; k++) acc[i][j][k] = 0.f;

    auto load_tile = [&](int j) {
        int s  = j / K64;
        uint32_t kb = (uint32_t)(j - s * K64) << 6;
        const __half* Ap = (s == 1) ? Al : Ah;
        const __half* Bp = (s == 2) ? Bl : Bh;
        int st = j % NSTAGE;
        uint32_t sa = sA[st];
        uint32_t sb = sB[st];
#pragma unroll
        for (int it = 0; it < 4; it++)
            cp16(sa + loff[it], Ap + rowA[it] + kb);
#pragma unroll
        for (int it = 0; it < 4; it++) {
            if (bok[it]) {
                cp16(sb + loff[it], Bp + rowB[it] + kb);
            } else {
                asm volatile("st.shared.v4.b32 [%0], {%1, %1, %1, %1};"
                             :: "r"(sb + loff[it]), "r"(0) : "memory");
            }
        }
    };

    load_tile(t0); CP_COMMIT();
    if (t0 + 1 < t1) { load_tile(t0 + 1); CP_COMMIT(); }

    for (int kt = t0; kt < t1; kt++) {
        if (kt + 1 < t1) { CP_WAIT(1); }
        else             { CP_WAIT(0); }
        __syncthreads();
        if (kt + 2 < t1) { load_tile(kt + 2); CP_COMMIT(); }

        uint32_t sa = sA[kt % NSTAGE], sb = sB[kt % NSTAGE];
#pragma unroll
        for (int ks = 0; ks < 4; ks++) {
            const uint32_t kx = (uint32_t)ks << 5;
            uint32_t a[2][4], b[4][4];
#pragma unroll
            for (int mt = 0; mt < 2; mt++)
                ldsm_x4(a[mt], sa + (aoff[mt] ^ kx));
#pragma unroll
            for (int bp = 0; bp < 4; bp++)
                ldsm_x4(b[bp], sb + (boff[bp] ^ kx));
#pragma unroll
            for (int mt = 0; mt < 2; mt++)
#pragma unroll
                for (int nt = 0; nt < 8; nt++)
                    mma16816(acc[mt][nt], a[mt], &b[nt >> 1][(nt & 1) * 2]);
        }
    }

    float* Cdst = C;
    int doep = ep;
    if (gridDim.z > 1) {
        Cdst = Cpart + (size_t)blockIdx.z * (size_t)(gridDim.y * 128) * ldc;
        doep = 0;
    }
#pragma unroll
    for (int mt = 0; mt < 2; mt++) {
#pragma unroll
        for (int nt = 0; nt < 8; nt++) {
            int c = bcol + nbase + nt * 8 + (lid & 3) * 2;
            if (c >= N) continue;
#pragma unroll
            for (int half = 0; half < 2; half++) {
                int r = brow + mbase + mt * 16 + (lid >> 2) + half * 8;
                float v0 = acc[mt][nt][half * 2 + 0];
                float v1 = acc[mt][nt][half * 2 + 1];
                if (doep == 1) {
                    v0 += bias[c];
                    v1 += bias[c + 1];
                    v0 = (v0 > 20.f) ? v0 : log1pf(__expf(v0));
                    v1 = (v1 > 20.f) ? v1 : log1pf(__expf(v1));
                }
                *(float2*)&Cdst[(size_t)r * ldc + c] = make_float2(v0, v1);
            }
        }
    }
}

// ---------------- split-K reduction for x_proj + fp16 re-split ---------------
__global__ __launch_bounds__(256)
void reduce_xproj(const float* __restrict__ part, float* __restrict__ xdbl,
                  __half* __restrict__ xdhi, __half* __restrict__ xdlo)
{
    int i = blockIdx.x * 256 + threadIdx.x;
    const int n4 = MROWS * XPC / 4;
    if (i >= n4) return;
    float4 s = ((const float4*)part)[i];
#pragma unroll
    for (int z = 1; z < ZSPLIT; z++) {
        float4 p = ((const float4*)(part + (size_t)z * MROWS * XPC))[i];
        s.x += p.x; s.y += p.y; s.z += p.z; s.w += p.w;
    }
    ((float4*)xdbl)[i] = s;
    __half h0 = __float2half(s.x), h1 = __float2half(s.y);
    __half h2 = __float2half(s.z), h3 = __float2half(s.w);
    __half2 H0; H0.x = h0; H0.y = h1;
    __half2 H1; H1.x = h2; H1.y = h3;
    ((__half2*)xdhi)[i*2+0] = H0;
    ((__half2*)xdhi)[i*2+1] = H1;
    __half2 L0, L1;
    L0.x = __float2half(s.x - __half2float(h0));
    L0.y = __float2half(s.y - __half2float(h1));
    L1.x = __float2half(s.z - __half2float(h2));
    L1.y = __float2half(s.w - __half2float(h3));
    ((__half2*)xdlo)[i*2+0] = L0;
    ((__half2*)xdlo)[i*2+1] = L1;
}

// ---------------- causal depthwise conv (width 4) + bias + silu -------------
__global__ __launch_bounds__(256)
void conv_silu_kernel(const float* __restrict__ xz,
                      const float* __restrict__ cw,
                      const float* __restrict__ cb,
                      float* __restrict__ u,
                      __half* __restrict__ uhi,
                      __half* __restrict__ ulo)
{
    int idx = blockIdx.x * 256 + threadIdx.x;
    if (idx >= BB*LL*DI) return;
    int d = idx & (DI - 1);
    int t = (idx >> 11) & (LL - 1);
    size_t base = (size_t)(idx >> 11) * (2*DI) + d;

    float w0 = cw[d*4+0], w1 = cw[d*4+1], w2 = cw[d*4+2], w3 = cw[d*4+3];
    float acc = cb[d];
    if (t >= 3) acc = fmaf(xz[base - 3*(size_t)(2*DI)], w0, acc);
    if (t >= 2) acc = fmaf(xz[base - 2*(size_t)(2*DI)], w1, acc);
    if (t >= 1) acc = fmaf(xz[base -   (size_t)(2*DI)], w2, acc);
    acc = fmaf(xz[base], w3, acc);

    float sig = 1.f / (1.f + __expf(-acc));
    float v = acc * sig;
    u[idx] = v;
    __half h = __float2half(v);
    uhi[idx] = h;
    ulo[idx] = __float2half(v - __half2float(h));
}

// ---------------- parallel scan, pass 1: chunk-local (P, S) ------------------
__global__ __launch_bounds__(128)
void scan_pass1(const float* __restrict__ delta,
                const float* __restrict__ u,
                const float* __restrict__ xdbl,
                const float* __restrict__ A_log,
                float* __restrict__ P, float* __restrict__ S)
{
    int gtid = blockIdx.x * 128 + threadIdx.x;
    int ch = gtid >> 4;
    int nq = gtid & 15;
    int b  = ch >> 11;
    int d  = ch & (DI - 1);
    int c  = blockIdx.y;

    const float An = -__expf(A_log[d*DS + nq]);
    float h = 0.f, sdt = 0.f;
    const size_t rbase = (size_t)b * LL + c * TC;

    float dtv = delta[rbase*DI + d];
    float uv  = u    [rbase*DI + d];
    float Bn  = xdbl [rbase*XPC + DTR + nq];

    for (int t = 0; t < TC; t++) {
        float dtv2 = 0.f, uv2 = 0.f, Bn2 = 0.f;
        if (t + 1 < TC) {
            size_t nrow = rbase + t + 1;
            dtv2 = delta[nrow*DI + d];
            uv2  = u    [nrow*DI + d];
            Bn2  = xdbl [nrow*XPC + DTR + nq];
        }
        sdt += dtv;
        float dA = __expf(dtv * An);
        h = fmaf(dA, h, (dtv * uv) * Bn);
        dtv = dtv2; uv = uv2; Bn = Bn2;
    }
    size_t o = ((size_t)c * MROWS + ch) * DS + nq;
    P[o] = __expf(An * sdt);
    S[o] = h;
}

// ---------------- parallel scan, combine ------------------------------------
__global__ __launch_bounds__(256)
void scan_combine(const float* __restrict__ P, const float* __restrict__ S,
                  float* __restrict__ H0)
{
    int i = blockIdx.x * 256 + threadIdx.x;
    if (i >= MROWS * DS) return;
    float h = 0.f;
    H0[i] = 0.f;
#pragma unroll
    for (int c = 0; c < NCHUNK - 1; c++) {
        size_t o = (size_t)c * MROWS * DS + i;
        h = fmaf(P[o], h, S[o]);
        H0[(size_t)(c+1) * MROWS * DS + i] = h;
    }
}

// ---------------- parallel scan, pass 2: outputs + skip + gate ---------------
__global__ __launch_bounds__(128)
void scan_pass2(const float* __restrict__ delta,
                const float* __restrict__ u,
                const float* __restrict__ xdbl,
                const float* __restrict__ xz,
                const float* __restrict__ A_log,
                const float* __restrict__ Dskip,
                const float* __restrict__ H0,
                __half* __restrict__ yghi,
                __half* __restrict__ yglo)
{
    int gtid = blockIdx.x * 128 + threadIdx.x;
    int ch = gtid >> 4;
    int nq = gtid & 15;
    int b  = ch >> 11;
    int d  = ch & (DI - 1);
    int c  = blockIdx.y;

    const float An = -__expf(A_log[d*DS + nq]);
    const float Dd = Dskip[d];
    float h = H0[((size_t)c * MROWS + ch) * DS + nq];
    const size_t rbase = (size_t)b * LL + c * TC;

    float dtv = delta[rbase*DI + d];
    float uv  = u    [rbase*DI + d];
    float Bn  = xdbl [rbase*XPC + DTR + nq];
    float Cn  = xdbl [rbase*XPC + DTR + DS + nq];
    float zv  = xz   [rbase*(2*DI) + DI + d];

    for (int t = 0; t < TC; t++) {
        float dtv2 = 0.f, uv2 = 0.f, Bn2 = 0.f, Cn2 = 0.f, zv2 = 0.f;
        if (t + 1 < TC) {
            size_t nrow = rbase + t + 1;
            dtv2 = delta[nrow*DI + d];
            uv2  = u    [nrow*DI + d];
            Bn2  = xdbl [nrow*XPC + DTR + nq];
            Cn2  = xdbl [nrow*XPC + DTR + DS + nq];
            zv2  = xz   [nrow*(2*DI) + DI + d];
        }

        float dA = __expf(dtv * An);
        h = fmaf(dA, h, (dtv * uv) * Bn);
        float yp = h * Cn;
        yp += __shfl_xor_sync(0xffffffffu, yp, 1);
        yp += __shfl_xor_sync(0xffffffffu, yp, 2);
        yp += __shfl_xor_sync(0xffffffffu, yp, 4);
        yp += __shfl_xor_sync(0xffffffffu, yp, 8);

        if (nq == 0) {
            float yfull = yp + uv * Dd;
            float sig = 1.f / (1.f + __expf(-zv));
            float g = yfull * (zv * sig);
            size_t o = (rbase + t)*DI + d;
            __half hh = __float2half(g);
            yghi[o] = hh;
            yglo[o] = __float2half(g - __half2float(hh));
        }
        dtv = dtv2; uv = uv2; Bn = Bn2; Cn = Cn2; zv = zv2;
    }
}

// ---------------- launch -----------------------------------------------------
extern "C" void kernel_launch(void* const* d_in, const int* in_sizes, int n_in,
                              void* d_out, int out_size)
{
    (void)in_sizes; (void)n_in; (void)out_size;
    const float* x       = (const float*)d_in[0];
    const float* W_in    = (const float*)d_in[1];
    const float* conv_w  = (const float*)d_in[2];
    const float* conv_b  = (const float*)d_in[3];
    const float* W_xproj = (const float*)d_in[4];
    const float* W_dt    = (const float*)d_in[5];
    const float* b_dt    = (const float*)d_in[6];
    const float* A_log   = (const float*)d_in[7];
    const float* Dskip   = (const float*)d_in[8];
    const float* W_out   = (const float*)d_in[9];
    float* out = (float*)d_out;

    float *xz, *u, *xdbl, *delta, *xpart, *Pb, *Sb, *H0b;
    __half *xhi, *xlo, *uhi, *ulo, *xdhi, *xdlo, *yghi, *yglo;
    __half *wih, *wxh, *wxl, *wdh, *wdl, *woh;
    cudaGetSymbolAddress((void**)&xz,    g_xz);
    cudaGetSymbolAddress((void**)&u,     g_u);
    cudaGetSymbolAddress((void**)&xdbl,  g_xdbl);
    cudaGetSymbolAddress((void**)&delta, g_delta);
    cudaGetSymbolAddress((void**)&xpart, g_xpart);
    cudaGetSymbolAddress((void**)&Pb,    g_P);
    cudaGetSymbolAddress((void**)&Sb,    g_S);
    cudaGetSymbolAddress((void**)&H0b,   g_H0);
    cudaGetSymbolAddress((void**)&xhi,   g_xhi);
    cudaGetSymbolAddress((void**)&xlo,   g_xlo);
    cudaGetSymbolAddress((void**)&uhi,   g_uhi);
    cudaGetSymbolAddress((void**)&ulo,   g_ulo);
    cudaGetSymbolAddress((void**)&xdhi,  g_xdhi);
    cudaGetSymbolAddress((void**)&xdlo,  g_xdlo);
    cudaGetSymbolAddress((void**)&yghi,  g_yghi);
    cudaGetSymbolAddress((void**)&yglo,  g_yglo);
    cudaGetSymbolAddress((void**)&wih,   g_wih);
    cudaGetSymbolAddress((void**)&wxh,   g_wxh);
    cudaGetSymbolAddress((void**)&wxl,   g_wxl);
    cudaGetSymbolAddress((void**)&wdh,   g_wdh);
    cudaGetSymbolAddress((void**)&wdl,   g_wdl);
    cudaGetSymbolAddress((void**)&woh,   g_woh);

    cudaFuncSetAttribute(mma_gemm, cudaFuncAttributeMaxDynamicSharedMemorySize, SMEM_DYN);

    const int BIG = 1 << 30;

    // launches 0-2 (gemm1 stays at profiled index 3)
    split2_f16<<<(MROWS*DM/4 + 255)/256, 256>>>(x,       xhi, xlo, MROWS*DM/4);
    cvt_f16   <<<(2*DI*DM/4  + 255)/256, 256>>>(W_in,    wih,      2*DI*DM/4);
    split2_f16<<<(XPC*DI/4   + 255)/256, 256>>>(W_xproj, wxh, wxl, XPC*DI/4);

    // 1) in_proj (2-seg; gate columns >= DI use 1-seg)   [ncu target]
    mma_gemm<<<dim3(32, 32, 1), 256, SMEM_DYN>>>(
        xhi, xlo, DM, wih, nullptr, DM, xz, 2*DI, 2*DI, DM/64, 2, DI,
        nullptr, 0, nullptr);

    split2_f16<<<(DI*DTR/4   + 255)/256, 256>>>(W_dt,    wdh, wdl, DI*DTR/4);
    cvt_f16   <<<(DM*DI/4    + 255)/256, 256>>>(W_out,   woh,      DM*DI/4);

    // 2) conv + silu -> u
    conv_silu_kernel<<<(BB*LL*DI + 255)/256, 256>>>(xz, conv_w, conv_b, u, uhi, ulo);
    // 3) x_proj (3-seg, 8-way split-K) + reduce
    mma_gemm<<<dim3(1, 32, ZSPLIT), 256, SMEM_DYN>>>(
        uhi, ulo, DI, wxh, wxl, DI, nullptr, XPC, XPC, DI/64, 3, BIG,
        nullptr, 0, xpart);
    reduce_xproj<<<(MROWS*XPC/4 + 255)/256, 256>>>(xpart, xdbl, xdhi, xdlo);
    // 4) delta = softplus(dt_low @ W_dt^T + b_dt)   (3-seg)
    mma_gemm<<<dim3(16, 32, 1), 256, SMEM_DYN>>>(
        xdhi, xdlo, XPC, wdh, wdl, DTR, delta, DI, DI, DTR/64, 3, BIG,
        b_dt, 1, nullptr);
    // 5) parallel selective scan (16 chunks)
    scan_pass1<<<dim3(512, NCHUNK), 128>>>(delta, u, xdbl, A_log, Pb, Sb);
    scan_combine<<<(MROWS*DS + 255)/256, 256>>>(Pb, Sb, H0b);
    scan_pass2<<<dim3(512, NCHUNK), 128>>>(delta, u, xdbl, xz, A_log, Dskip,
                                           H0b, yghi, yglo);
    // 6) out_proj (2-seg)
    mma_gemm<<<dim3(8, 32, 1), 256, SMEM_DYN>>>(
        yghi, yglo, DI, woh, nullptr, DI, out, DM, DM, DI/64, 2, BIG,
        nullptr, 0, nullptr);
}